// round 6
// baseline (speedup 1.0000x reference)
#include <cuda_runtime.h>

// Problem constants
#define S_LEN  2048
#define DM     1024
#define NH     16
#define DKH    64
#define BATCH  2
#define NTOK   (BATCH * S_LEN)   // 4096

// Scratch (allocation-free rule: __device__ globals)
__device__ float g_Qp[(size_t)NTOK * DM];    // projected Q  [B*S, D]
__device__ float g_Kp[(size_t)NTOK * DKH];   // projected K  [B*S, d_k]
__device__ float g_Vp[(size_t)NTOK * DKH];   // projected V  [B*S, d_k]
__device__ float g_Xo[(size_t)NTOK * DM];    // attention out [B*S, D]

// ---------------------------------------------------------------------------
// Small GEMM (K/V projections, N=64):
// C[M,N] = A[M,K] @ B[K,N] + bias[N]; 64x64 tile, BK=16, 256 thr, 4x4 micro.
// ---------------------------------------------------------------------------
__global__ __launch_bounds__(256) void gemm_bias_kernel(
    const float* __restrict__ A, const float* __restrict__ B,
    const float* __restrict__ bias, float* __restrict__ C,
    int M, int N, int K)
{
    __shared__ float As[16][68];
    __shared__ float Bs[16][68];

    const int tid = threadIdx.x;
    const int tx  = tid & 15;
    const int ty  = tid >> 4;
    const int m0  = blockIdx.y << 6;
    const int n0  = blockIdx.x << 6;

    const int ar = tid >> 2;
    const int ak = (tid & 3) << 2;
    const int br = tid >> 4;
    const int bn = (tid & 15) << 2;

    float acc[4][4];
#pragma unroll
    for (int i = 0; i < 4; i++)
#pragma unroll
        for (int j = 0; j < 4; j++) acc[i][j] = 0.0f;

    for (int k0 = 0; k0 < K; k0 += 16) {
        float4 a = *(const float4*)(A + (size_t)(m0 + ar) * K + (k0 + ak));
        float4 b = *(const float4*)(B + (size_t)(k0 + br) * N + (n0 + bn));
        As[ak + 0][ar] = a.x;
        As[ak + 1][ar] = a.y;
        As[ak + 2][ar] = a.z;
        As[ak + 3][ar] = a.w;
        *(float4*)&Bs[br][bn] = b;
        __syncthreads();

#pragma unroll
        for (int kk = 0; kk < 16; kk++) {
            float4 av = *(const float4*)&As[kk][ty << 2];
            float4 bv = *(const float4*)&Bs[kk][tx << 2];
            acc[0][0] += av.x * bv.x; acc[0][1] += av.x * bv.y;
            acc[0][2] += av.x * bv.z; acc[0][3] += av.x * bv.w;
            acc[1][0] += av.y * bv.x; acc[1][1] += av.y * bv.y;
            acc[1][2] += av.y * bv.z; acc[1][3] += av.y * bv.w;
            acc[2][0] += av.z * bv.x; acc[2][1] += av.z * bv.y;
            acc[2][2] += av.z * bv.z; acc[2][3] += av.z * bv.w;
            acc[3][0] += av.w * bv.x; acc[3][1] += av.w * bv.y;
            acc[3][2] += av.w * bv.z; acc[3][3] += av.w * bv.w;
        }
        __syncthreads();
    }

    float4 bb = *(const float4*)(bias + n0 + (tx << 2));
#pragma unroll
    for (int i = 0; i < 4; i++) {
        float4 o;
        o.x = acc[i][0] + bb.x;
        o.y = acc[i][1] + bb.y;
        o.z = acc[i][2] + bb.z;
        o.w = acc[i][3] + bb.w;
        *(float4*)(C + (size_t)(m0 + (ty << 2) + i) * N + n0 + (tx << 2)) = o;
    }
}

// ---------------------------------------------------------------------------
// Big GEMM for Q and O projections (N multiple of 128):
// 128x128 tile, BK=16, 256 threads, 8x8 micro-tile -> 16 FMA per LDS.128.
// ---------------------------------------------------------------------------
__global__ __launch_bounds__(256, 2) void gemm128_bias_kernel(
    const float* __restrict__ A, const float* __restrict__ B,
    const float* __restrict__ bias, float* __restrict__ C,
    int M, int N, int K)
{
    __shared__ float As[16][132];   // A^T: As[k][m]
    __shared__ float Bs[16][132];   // B:   Bs[k][n]

    const int tid = threadIdx.x;
    const int tx  = tid & 15;       // n-group (8 cols each)
    const int ty  = tid >> 4;       // m-group (8 rows each)
    const int m0  = blockIdx.y << 7;
    const int n0  = blockIdx.x << 7;

    const int ar  = tid >> 1;             // 0..127
    const int ak  = (tid & 1) << 3;       // 0 or 8
    const int br  = tid >> 4;             // 0..15
    const int bn  = (tid & 15) << 3;      // 0..120

    float acc[8][8];
#pragma unroll
    for (int i = 0; i < 8; i++)
#pragma unroll
        for (int j = 0; j < 8; j++) acc[i][j] = 0.0f;

    for (int k0 = 0; k0 < K; k0 += 16) {
        float4 a0 = *(const float4*)(A + (size_t)(m0 + ar) * K + (k0 + ak));
        float4 a1 = *(const float4*)(A + (size_t)(m0 + ar) * K + (k0 + ak + 4));
        float4 b0 = *(const float4*)(B + (size_t)(k0 + br) * N + (n0 + bn));
        float4 b1 = *(const float4*)(B + (size_t)(k0 + br) * N + (n0 + bn + 4));
        As[ak + 0][ar] = a0.x; As[ak + 1][ar] = a0.y;
        As[ak + 2][ar] = a0.z; As[ak + 3][ar] = a0.w;
        As[ak + 4][ar] = a1.x; As[ak + 5][ar] = a1.y;
        As[ak + 6][ar] = a1.z; As[ak + 7][ar] = a1.w;
        *(float4*)&Bs[br][bn]     = b0;
        *(float4*)&Bs[br][bn + 4] = b1;
        __syncthreads();

#pragma unroll
        for (int kk = 0; kk < 16; kk++) {
            float a[8], b[8];
            *(float4*)&a[0] = *(const float4*)&As[kk][(ty << 3) + 0];
            *(float4*)&a[4] = *(const float4*)&As[kk][(ty << 3) + 4];
            *(float4*)&b[0] = *(const float4*)&Bs[kk][(tx << 3) + 0];
            *(float4*)&b[4] = *(const float4*)&Bs[kk][(tx << 3) + 4];
#pragma unroll
            for (int i = 0; i < 8; i++)
#pragma unroll
                for (int j = 0; j < 8; j++)
                    acc[i][j] += a[i] * b[j];
        }
        __syncthreads();
    }

    float4 bb0 = *(const float4*)(bias + n0 + (tx << 3));
    float4 bb1 = *(const float4*)(bias + n0 + (tx << 3) + 4);
#pragma unroll
    for (int i = 0; i < 8; i++) {
        float4 o0, o1;
        o0.x = acc[i][0] + bb0.x; o0.y = acc[i][1] + bb0.y;
        o0.z = acc[i][2] + bb0.z; o0.w = acc[i][3] + bb0.w;
        o1.x = acc[i][4] + bb1.x; o1.y = acc[i][5] + bb1.y;
        o1.z = acc[i][6] + bb1.z; o1.w = acc[i][7] + bb1.w;
        float* cp = C + (size_t)(m0 + (ty << 3) + i) * N + n0 + (tx << 3);
        *(float4*)cp       = o0;
        *(float4*)(cp + 4) = o1;
    }
}

// ---------------------------------------------------------------------------
// Fused masked MQA attention, fp32, flash-style online softmax.
// One block = (b, h, 128-row q-tile); K-tiles of 64. 256 threads.
// Micro-tile 4(q) x 8(k) for scores, 4(q) x 8(d) for output.
// Smem: Qs[64][132] (Q^T), Ks[64][68] (K^T), Vs[64][68] (V), Ps[64][132] (P^T)
// P^T is stored as float4 q-chunks with XOR swizzle on the chunk index
// (chunk c = ty ^ (row>>3)) so STS.128 spreads over banks and the PV-loop
// LDS.128 (same swizzle) stays broadcast/conflict-free.
// ---------------------------------------------------------------------------
#define QT   128          // q rows per block
#define KT   64           // k cols per tile
#define QPAD 132
#define PPAD 132

__global__ __launch_bounds__(256, 2) void attn_kernel(const int* __restrict__ mask)
{
    extern __shared__ float sm[];
    float* Qs = sm;                                  // [64][QPAD]
    float* Ks = Qs + 64 * QPAD;                      // [64][68]
    float* Vs = Ks + 64 * 68;                        // [64][68]
    float* Ps = Vs + 64 * 68;                        // [64][PPAD]

    const int tid = threadIdx.x;
    const int tx  = tid & 7;        // k-group / d-group (8 wide)
    const int ty  = tid >> 3;       // q-group (0..31, 4 rows each)
    const int q0  = blockIdx.x * QT;
    const int h   = blockIdx.y;
    const int b   = blockIdx.z;

    const float* Qb = g_Qp + (size_t)b * S_LEN * DM + h * DKH;
    const float* Kb = g_Kp + (size_t)b * S_LEN * DKH;
    const float* Vb = g_Vp + (size_t)b * S_LEN * DKH;
    const int*   Mb = mask + (size_t)b * S_LEN * S_LEN;

    // Load Q tile transposed: Qs[d][q]  (128 rows x 64 d = 2048 float4, 8/thr)
    {
        const int c = (tid & 15) << 2;     // d-chunk
        const int r = tid >> 4;            // base row
#pragma unroll
        for (int it = 0; it < 8; it++) {
            const int q = r + (it << 4);
            float4 v = *(const float4*)(Qb + (size_t)(q0 + q) * DM + c);
            Qs[(c + 0) * QPAD + q] = v.x;
            Qs[(c + 1) * QPAD + q] = v.y;
            Qs[(c + 2) * QPAD + q] = v.z;
            Qs[(c + 3) * QPAD + q] = v.w;
        }
    }

    float m_i[4], l_i[4], o[4][8];
#pragma unroll
    for (int i = 0; i < 4; i++) {
        m_i[i] = -3.0e38f;
        l_i[i] = 0.0f;
#pragma unroll
        for (int j = 0; j < 8; j++) o[i][j] = 0.0f;
    }

    for (int k0 = 0; k0 < S_LEN; k0 += KT) {
        __syncthreads();   // prior PV reads of Ks/Vs/Ps done; Qs visible (1st iter)

        // Load K tile transposed Ks[d][k], and V tile natural Vs[k][d]
        {
            const int c = (tid & 15) << 2;
            const int r = tid >> 4;
#pragma unroll
            for (int it = 0; it < 4; it++) {
                const int k = r + (it << 4);
                float4 kv = *(const float4*)(Kb + (size_t)(k0 + k) * DKH + c);
                Ks[(c + 0) * 68 + k] = kv.x;
                Ks[(c + 1) * 68 + k] = kv.y;
                Ks[(c + 2) * 68 + k] = kv.z;
                Ks[(c + 3) * 68 + k] = kv.w;
                *(float4*)&Vs[k * 68 + c] =
                    *(const float4*)(Vb + (size_t)(k0 + k) * DKH + c);
            }
        }
        __syncthreads();

        // S = Q K^T : thread rows q0+ty*4+i, cols k0+tx*8+j
        float s[4][8];
#pragma unroll
        for (int i = 0; i < 4; i++)
#pragma unroll
            for (int j = 0; j < 8; j++) s[i][j] = 0.0f;

#pragma unroll 8
        for (int d = 0; d < 64; d++) {
            float a[4], bb[8];
            *(float4*)&a[0]  = *(const float4*)&Qs[d * QPAD + (ty << 2)];
            *(float4*)&bb[0] = *(const float4*)&Ks[d * 68 + (tx << 3)];
            *(float4*)&bb[4] = *(const float4*)&Ks[d * 68 + (tx << 3) + 4];
#pragma unroll
            for (int i = 0; i < 4; i++)
#pragma unroll
                for (int j = 0; j < 8; j++)
                    s[i][j] += a[i] * bb[j];
        }

        // scale + mask
#pragma unroll
        for (int i = 0; i < 4; i++) {
            const int* mrow = Mb + (size_t)(q0 + (ty << 2) + i) * S_LEN + k0 + (tx << 3);
            const int4 m0v = *(const int4*)(mrow);
            const int4 m1v = *(const int4*)(mrow + 4);
            s[i][0] = m0v.x ? s[i][0] * 0.125f : -1.0e9f;
            s[i][1] = m0v.y ? s[i][1] * 0.125f : -1.0e9f;
            s[i][2] = m0v.z ? s[i][2] * 0.125f : -1.0e9f;
            s[i][3] = m0v.w ? s[i][3] * 0.125f : -1.0e9f;
            s[i][4] = m1v.x ? s[i][4] * 0.125f : -1.0e9f;
            s[i][5] = m1v.y ? s[i][5] * 0.125f : -1.0e9f;
            s[i][6] = m1v.z ? s[i][6] * 0.125f : -1.0e9f;
            s[i][7] = m1v.w ? s[i][7] * 0.125f : -1.0e9f;
        }

        // Online softmax: row q=ty*4+i spread over 8 lanes (tx=0..7, xor 1/2/4)
#pragma unroll
        for (int i = 0; i < 4; i++) {
            float mx = s[i][0];
#pragma unroll
            for (int j = 1; j < 8; j++) mx = fmaxf(mx, s[i][j]);
            mx = fmaxf(mx, __shfl_xor_sync(0xffffffffu, mx, 1));
            mx = fmaxf(mx, __shfl_xor_sync(0xffffffffu, mx, 2));
            mx = fmaxf(mx, __shfl_xor_sync(0xffffffffu, mx, 4));
            const float mnew = fmaxf(m_i[i], mx);
            const float corr = __expf(m_i[i] - mnew);
            m_i[i] = mnew;
            float rs = 0.0f;
#pragma unroll
            for (int j = 0; j < 8; j++) {
                s[i][j] = __expf(s[i][j] - mnew);
                rs += s[i][j];
            }
            rs += __shfl_xor_sync(0xffffffffu, rs, 1);
            rs += __shfl_xor_sync(0xffffffffu, rs, 2);
            rs += __shfl_xor_sync(0xffffffffu, rs, 4);
            l_i[i] = l_i[i] * corr + rs;
#pragma unroll
            for (int j = 0; j < 8; j++) o[i][j] *= corr;
        }

        // Store P^T: row r=tx*8+j, q-chunk swizzled c = ty ^ (r>>3) = ty ^ tx
        {
            const int c4 = (ty ^ tx) << 2;
#pragma unroll
            for (int j = 0; j < 8; j++) {
                const int r = (tx << 3) + j;
                float4 p;
                p.x = s[0][j]; p.y = s[1][j]; p.z = s[2][j]; p.w = s[3][j];
                *(float4*)&Ps[r * PPAD + c4] = p;
            }
        }
        __syncthreads();

        // O += P V : thread rows q=ty*4+i, dims d=tx*8+j
#pragma unroll 8
        for (int kk = 0; kk < KT; kk++) {
            float a[4], vv[8];
            *(float4*)&a[0]  = *(const float4*)&Ps[kk * PPAD + ((ty ^ (kk >> 3)) << 2)];
            *(float4*)&vv[0] = *(const float4*)&Vs[kk * 68 + (tx << 3)];
            *(float4*)&vv[4] = *(const float4*)&Vs[kk * 68 + (tx << 3) + 4];
#pragma unroll
            for (int i = 0; i < 4; i++)
#pragma unroll
                for (int j = 0; j < 8; j++)
                    o[i][j] += a[i] * vv[j];
        }
    }

    // Epilogue: normalize, write g_Xo[b, q, h*64 + d]
#pragma unroll
    for (int i = 0; i < 4; i++) {
        const float inv = 1.0f / l_i[i];
        float4 r0, r1;
        r0.x = o[i][0] * inv; r0.y = o[i][1] * inv;
        r0.z = o[i][2] * inv; r0.w = o[i][3] * inv;
        r1.x = o[i][4] * inv; r1.y = o[i][5] * inv;
        r1.z = o[i][6] * inv; r1.w = o[i][7] * inv;
        float* op = g_Xo + (size_t)(b * S_LEN + q0 + (ty << 2) + i) * DM
                    + h * DKH + (tx << 3);
        *(float4*)op       = r0;
        *(float4*)(op + 4) = r1;
    }
}

// ---------------------------------------------------------------------------
extern "C" void kernel_launch(void* const* d_in, const int* in_sizes, int n_in,
                              void* d_out, int out_size)
{
    const float* query = (const float*)d_in[0];
    const float* key   = (const float*)d_in[1];
    const float* value = (const float*)d_in[2];
    const int*   mask  = (const int*)  d_in[3];
    const float* Wq    = (const float*)d_in[4];
    const float* bq    = (const float*)d_in[5];
    const float* Wk    = (const float*)d_in[6];
    const float* bk    = (const float*)d_in[7];
    const float* Wv    = (const float*)d_in[8];
    const float* bv    = (const float*)d_in[9];
    const float* Wo    = (const float*)d_in[10];
    const float* bo    = (const float*)d_in[11];
    float* out = (float*)d_out;

    float *qp, *kp, *vp, *xo;
    cudaGetSymbolAddress((void**)&qp, g_Qp);
    cudaGetSymbolAddress((void**)&kp, g_Kp);
    cudaGetSymbolAddress((void**)&vp, g_Vp);
    cudaGetSymbolAddress((void**)&xo, g_Xo);

    const int attn_smem = (64 * QPAD + 64 * 68 + 64 * 68 + 64 * PPAD)
                          * (int)sizeof(float);   // 102400 B
    cudaFuncSetAttribute(attn_kernel,
                         cudaFuncAttributeMaxDynamicSharedMemorySize, attn_smem);

    dim3 blk(256);
    // Q projection: [4096,1024] @ [1024,1024] + bq   (128x128 tiles)
    gemm128_bias_kernel<<<dim3(DM / 128, NTOK / 128), blk>>>(query, Wq, bq, qp, NTOK, DM, DM);
    // K/V projections: [4096,1024] @ [1024,64]       (64x64 tiles)
    gemm_bias_kernel<<<dim3(DKH / 64, NTOK / 64), blk>>>(key, Wk, bk, kp, NTOK, DKH, DM);
    gemm_bias_kernel<<<dim3(DKH / 64, NTOK / 64), blk>>>(value, Wv, bv, vp, NTOK, DKH, DM);
    // Fused masked MQA attention
    attn_kernel<<<dim3(S_LEN / QT, NH, BATCH), blk, attn_smem>>>(mask);
    // Output projection
    gemm128_bias_kernel<<<dim3(DM / 128, NTOK / 128), blk>>>(xo, Wo, bo, out, NTOK, DM, DM);
}

// round 8
// speedup vs baseline: 1.6350x; 1.6350x over previous
#include <cuda_runtime.h>
#include <cstdint>

// Problem constants
#define S_LEN  2048
#define DM     1024
#define NH     16
#define DKH    64
#define BATCH  2
#define NTOK   (BATCH * S_LEN)   // 4096

// Scratch (allocation-free rule: __device__ globals)
__device__ float g_Qp[(size_t)NTOK * DM];    // projected Q  [B*S, D]
__device__ float g_Kp[(size_t)NTOK * DKH];   // projected K  [B*S, d_k]
__device__ float g_Vp[(size_t)NTOK * DKH];   // projected V  [B*S, d_k]
__device__ float g_Xo[(size_t)NTOK * DM];    // attention out [B*S, D]

// ---------------------------------------------------------------------------
// helpers
// ---------------------------------------------------------------------------
__device__ __forceinline__ uint32_t f2tf32(float x) {
    uint32_t r;
    asm("cvt.rna.tf32.f32 %0, %1;" : "=r"(r) : "f"(x));
    return r;
}
__device__ __forceinline__ float tf32r(float x) {
    return __uint_as_float(f2tf32(x));
}

// exp2 on the FMA pipe (no MUFU): round-to-nearest split + deg-5 Taylor on
// [-0.5, 0.5] (rel err ~2.4e-6), exponent via bit-splice. x <= 0 expected;
// clamp keeps the bit-splice in normal range and sends -inf-ish to ~0.
__device__ __forceinline__ float exp2_fast(float x) {
    x = fmaxf(x, -126.0f);
    int   i = __float2int_rn(x);
    float f = x - (float)i;
    float p = 0.0013333558f;
    p = fmaf(p, f, 0.0096181291f);
    p = fmaf(p, f, 0.0555041087f);
    p = fmaf(p, f, 0.2402265070f);
    p = fmaf(p, f, 0.6931471806f);
    p = fmaf(p, f, 1.0f);
    return p * __int_as_float((i + 127) << 23);
}

__device__ __forceinline__ void mma_tf32(float c[4], const uint32_t a[4],
                                         uint32_t b0, uint32_t b1) {
    asm volatile(
        "mma.sync.aligned.m16n8k8.row.col.f32.tf32.tf32.f32 "
        "{%0,%1,%2,%3}, {%4,%5,%6,%7}, {%8,%9}, {%0,%1,%2,%3};\n"
        : "+f"(c[0]), "+f"(c[1]), "+f"(c[2]), "+f"(c[3])
        : "r"(a[0]), "r"(a[1]), "r"(a[2]), "r"(a[3]), "r"(b0), "r"(b1));
}

// ---------------------------------------------------------------------------
// Small GEMM (K/V projections, N=64):
// ---------------------------------------------------------------------------
__global__ __launch_bounds__(256) void gemm_bias_kernel(
    const float* __restrict__ A, const float* __restrict__ B,
    const float* __restrict__ bias, float* __restrict__ C,
    int M, int N, int K)
{
    __shared__ float As[16][68];
    __shared__ float Bs[16][68];

    const int tid = threadIdx.x;
    const int tx  = tid & 15;
    const int ty  = tid >> 4;
    const int m0  = blockIdx.y << 6;
    const int n0  = blockIdx.x << 6;

    const int ar = tid >> 2;
    const int ak = (tid & 3) << 2;
    const int br = tid >> 4;
    const int bn = (tid & 15) << 2;

    float acc[4][4];
#pragma unroll
    for (int i = 0; i < 4; i++)
#pragma unroll
        for (int j = 0; j < 4; j++) acc[i][j] = 0.0f;

    for (int k0 = 0; k0 < K; k0 += 16) {
        float4 a = *(const float4*)(A + (size_t)(m0 + ar) * K + (k0 + ak));
        float4 b = *(const float4*)(B + (size_t)(k0 + br) * N + (n0 + bn));
        As[ak + 0][ar] = a.x;
        As[ak + 1][ar] = a.y;
        As[ak + 2][ar] = a.z;
        As[ak + 3][ar] = a.w;
        *(float4*)&Bs[br][bn] = b;
        __syncthreads();

#pragma unroll
        for (int kk = 0; kk < 16; kk++) {
            float4 av = *(const float4*)&As[kk][ty << 2];
            float4 bv = *(const float4*)&Bs[kk][tx << 2];
            acc[0][0] += av.x * bv.x; acc[0][1] += av.x * bv.y;
            acc[0][2] += av.x * bv.z; acc[0][3] += av.x * bv.w;
            acc[1][0] += av.y * bv.x; acc[1][1] += av.y * bv.y;
            acc[1][2] += av.y * bv.z; acc[1][3] += av.y * bv.w;
            acc[2][0] += av.z * bv.x; acc[2][1] += av.z * bv.y;
            acc[2][2] += av.z * bv.z; acc[2][3] += av.z * bv.w;
            acc[3][0] += av.w * bv.x; acc[3][1] += av.w * bv.y;
            acc[3][2] += av.w * bv.z; acc[3][3] += av.w * bv.w;
        }
        __syncthreads();
    }

    float4 bb = *(const float4*)(bias + n0 + (tx << 2));
#pragma unroll
    for (int i = 0; i < 4; i++) {
        float4 o;
        o.x = acc[i][0] + bb.x;
        o.y = acc[i][1] + bb.y;
        o.z = acc[i][2] + bb.z;
        o.w = acc[i][3] + bb.w;
        *(float4*)(C + (size_t)(m0 + (ty << 2) + i) * N + n0 + (tx << 2)) = o;
    }
}

// ---------------------------------------------------------------------------
// Big GEMM for Q and O projections (128x128 tile, 8x8 micro-tile)
// ---------------------------------------------------------------------------
__global__ __launch_bounds__(256, 2) void gemm128_bias_kernel(
    const float* __restrict__ A, const float* __restrict__ B,
    const float* __restrict__ bias, float* __restrict__ C,
    int M, int N, int K)
{
    __shared__ float As[16][132];   // A^T: As[k][m]
    __shared__ float Bs[16][132];   // B:   Bs[k][n]

    const int tid = threadIdx.x;
    const int tx  = tid & 15;
    const int ty  = tid >> 4;
    const int m0  = blockIdx.y << 7;
    const int n0  = blockIdx.x << 7;

    const int ar  = tid >> 1;
    const int ak  = (tid & 1) << 3;
    const int br  = tid >> 4;
    const int bn  = (tid & 15) << 3;

    float acc[8][8];
#pragma unroll
    for (int i = 0; i < 8; i++)
#pragma unroll
        for (int j = 0; j < 8; j++) acc[i][j] = 0.0f;

    for (int k0 = 0; k0 < K; k0 += 16) {
        float4 a0 = *(const float4*)(A + (size_t)(m0 + ar) * K + (k0 + ak));
        float4 a1 = *(const float4*)(A + (size_t)(m0 + ar) * K + (k0 + ak + 4));
        float4 b0 = *(const float4*)(B + (size_t)(k0 + br) * N + (n0 + bn));
        float4 b1 = *(const float4*)(B + (size_t)(k0 + br) * N + (n0 + bn + 4));
        As[ak + 0][ar] = a0.x; As[ak + 1][ar] = a0.y;
        As[ak + 2][ar] = a0.z; As[ak + 3][ar] = a0.w;
        As[ak + 4][ar] = a1.x; As[ak + 5][ar] = a1.y;
        As[ak + 6][ar] = a1.z; As[ak + 7][ar] = a1.w;
        *(float4*)&Bs[br][bn]     = b0;
        *(float4*)&Bs[br][bn + 4] = b1;
        __syncthreads();

#pragma unroll
        for (int kk = 0; kk < 16; kk++) {
            float a[8], b[8];
            *(float4*)&a[0] = *(const float4*)&As[kk][(ty << 3) + 0];
            *(float4*)&a[4] = *(const float4*)&As[kk][(ty << 3) + 4];
            *(float4*)&b[0] = *(const float4*)&Bs[kk][(tx << 3) + 0];
            *(float4*)&b[4] = *(const float4*)&Bs[kk][(tx << 3) + 4];
#pragma unroll
            for (int i = 0; i < 8; i++)
#pragma unroll
                for (int j = 0; j < 8; j++)
                    acc[i][j] += a[i] * b[j];
        }
        __syncthreads();
    }

    float4 bb0 = *(const float4*)(bias + n0 + (tx << 3));
    float4 bb1 = *(const float4*)(bias + n0 + (tx << 3) + 4);
#pragma unroll
    for (int i = 0; i < 8; i++) {
        float4 o0, o1;
        o0.x = acc[i][0] + bb0.x; o0.y = acc[i][1] + bb0.y;
        o0.z = acc[i][2] + bb0.z; o0.w = acc[i][3] + bb0.w;
        o1.x = acc[i][4] + bb1.x; o1.y = acc[i][5] + bb1.y;
        o1.z = acc[i][6] + bb1.z; o1.w = acc[i][7] + bb1.w;
        float* cp = C + (size_t)(m0 + (ty << 3) + i) * N + n0 + (tx << 3);
        *(float4*)cp       = o0;
        *(float4*)(cp + 4) = o1;
    }
}

// ---------------------------------------------------------------------------
// Fused masked MQA attention — tf32 mma.sync tensor cores.
// Block: 128 threads / 4 warps, 64 q-rows (warp w owns rows w*16..w*16+15).
// K-tiles of 64. Q lives in A-fragments (scaled by 0.125*log2e).
// Smem: Kv[k][d] natural (score B-frags conflict-free with pad 68),
//       Vt[d][k] transposed (PV B-frags conflict-free).
// Softmax: base-2 domain, FMA-only exp2 (no MUFU), C-frag row reductions via
// quad shuffles. P C-frag -> A-frag via quad shuffles (no smem round-trip).
// ---------------------------------------------------------------------------
#define KPAD 68

__global__ __launch_bounds__(128, 3) void attn_mma_kernel(const int* __restrict__ mask)
{
    __shared__ float Kv[64][KPAD];   // Kv[kseq][d]
    __shared__ float Vt[64][KPAD];   // Vt[d][kseq]

    const int tid  = threadIdx.x;
    const int lane = tid & 31;
    const int warp = tid >> 5;
    const int g    = lane >> 2;      // group id (0..7)
    const int t4   = lane & 3;       // thread-in-group
    const int q0   = blockIdx.x << 6;
    const int h    = blockIdx.y;
    const int b    = blockIdx.z;

    const float* Qb = g_Qp + (size_t)b * S_LEN * DM + h * DKH;
    const float* Kb = g_Kp + (size_t)b * S_LEN * DKH;
    const float* Vb = g_Vp + (size_t)b * S_LEN * DKH;
    const int*   Mb = mask + (size_t)b * S_LEN * S_LEN;

    // Q A-fragments: rows r0 = q0 + warp*16 + g, r1 = r0 + 8.
    // Fold 1/sqrt(64) and log2(e): scores come out in base-2 domain.
    const int r0 = q0 + warp * 16 + g;
    const int r1 = r0 + 8;
    const float qsc = 0.125f * 1.4426950408889634f;
    uint32_t qa[8][4];
#pragma unroll
    for (int s = 0; s < 8; s++) {
        qa[s][0] = f2tf32(Qb[(size_t)r0 * DM + s * 8 + t4]     * qsc);
        qa[s][1] = f2tf32(Qb[(size_t)r1 * DM + s * 8 + t4]     * qsc);
        qa[s][2] = f2tf32(Qb[(size_t)r0 * DM + s * 8 + t4 + 4] * qsc);
        qa[s][3] = f2tf32(Qb[(size_t)r1 * DM + s * 8 + t4 + 4] * qsc);
    }

    float m0 = -1e30f, m1 = -1e30f, l0 = 0.0f, l1 = 0.0f;
    float of[8][4];
#pragma unroll
    for (int nb = 0; nb < 8; nb++)
#pragma unroll
        for (int r = 0; r < 4; r++) of[nb][r] = 0.0f;

    for (int k0 = 0; k0 < S_LEN; k0 += 64) {
        __syncthreads();
        // Load K tile (natural) and V tile (transposed), tf32-rounded.
        {
            const int r  = tid >> 1;            // 0..63 (kseq row)
            const int cb = (tid & 1) * 8;       // float4 chunk base
#pragma unroll
            for (int i = 0; i < 8; i++) {
                const int c = (cb + i) * 4;     // d col base
                float4 kv = *(const float4*)(Kb + (size_t)(k0 + r) * DKH + c);
                Kv[r][c + 0] = tf32r(kv.x);
                Kv[r][c + 1] = tf32r(kv.y);
                Kv[r][c + 2] = tf32r(kv.z);
                Kv[r][c + 3] = tf32r(kv.w);
                float4 vv = *(const float4*)(Vb + (size_t)(k0 + r) * DKH + c);
                Vt[c + 0][r] = tf32r(vv.x);
                Vt[c + 1][r] = tf32r(vv.y);
                Vt[c + 2][r] = tf32r(vv.z);
                Vt[c + 3][r] = tf32r(vv.w);
            }
        }
        __syncthreads();

        // Scores: sc[j] = 16x8 C-frag for n-block j (cols k0+j*8..+7)
        float sc[8][4];
#pragma unroll
        for (int j = 0; j < 8; j++) {
            sc[j][0] = sc[j][1] = sc[j][2] = sc[j][3] = 0.0f;
#pragma unroll
            for (int s = 0; s < 8; s++) {
                uint32_t b0 = __float_as_uint(Kv[j * 8 + g][s * 8 + t4]);
                uint32_t b1 = __float_as_uint(Kv[j * 8 + g][s * 8 + t4 + 4]);
                mma_tf32(sc[j], qa[s], b0, b1);
            }
        }

        // Mask (C-frag: c0/c1 row r0 cols 2*t4,2*t4+1; c2/c3 row r1)
#pragma unroll
        for (int j = 0; j < 8; j++) {
            const int c0 = k0 + j * 8 + t4 * 2;
            int2 mA = *(const int2*)(Mb + (size_t)r0 * S_LEN + c0);
            int2 mB = *(const int2*)(Mb + (size_t)r1 * S_LEN + c0);
            sc[j][0] = mA.x ? sc[j][0] : -1.0e9f;
            sc[j][1] = mA.y ? sc[j][1] : -1.0e9f;
            sc[j][2] = mB.x ? sc[j][2] : -1.0e9f;
            sc[j][3] = mB.y ? sc[j][3] : -1.0e9f;
        }

        // Online softmax (base-2). Row r0 -> regs 0,1; row r1 -> regs 2,3.
        float mx0 = -1e30f, mx1 = -1e30f;
#pragma unroll
        for (int j = 0; j < 8; j++) {
            mx0 = fmaxf(mx0, fmaxf(sc[j][0], sc[j][1]));
            mx1 = fmaxf(mx1, fmaxf(sc[j][2], sc[j][3]));
        }
        mx0 = fmaxf(mx0, __shfl_xor_sync(0xffffffffu, mx0, 1));
        mx0 = fmaxf(mx0, __shfl_xor_sync(0xffffffffu, mx0, 2));
        mx1 = fmaxf(mx1, __shfl_xor_sync(0xffffffffu, mx1, 1));
        mx1 = fmaxf(mx1, __shfl_xor_sync(0xffffffffu, mx1, 2));

        const float mn0 = fmaxf(m0, mx0);
        const float mn1 = fmaxf(m1, mx1);
        const float corr0 = exp2_fast(m0 - mn0);
        const float corr1 = exp2_fast(m1 - mn1);
        m0 = mn0; m1 = mn1;

        float rs0 = 0.0f, rs1 = 0.0f;
#pragma unroll
        for (int j = 0; j < 8; j++) {
            sc[j][0] = exp2_fast(sc[j][0] - m0);
            sc[j][1] = exp2_fast(sc[j][1] - m0);
            sc[j][2] = exp2_fast(sc[j][2] - m1);
            sc[j][3] = exp2_fast(sc[j][3] - m1);
            rs0 += sc[j][0] + sc[j][1];
            rs1 += sc[j][2] + sc[j][3];
        }
        rs0 += __shfl_xor_sync(0xffffffffu, rs0, 1);
        rs0 += __shfl_xor_sync(0xffffffffu, rs0, 2);
        rs1 += __shfl_xor_sync(0xffffffffu, rs1, 1);
        rs1 += __shfl_xor_sync(0xffffffffu, rs1, 2);
        l0 = l0 * corr0 + rs0;
        l1 = l1 * corr1 + rs1;

#pragma unroll
        for (int nb = 0; nb < 8; nb++) {
            of[nb][0] *= corr0; of[nb][1] *= corr0;
            of[nb][2] *= corr1; of[nb][3] *= corr1;
        }

        // PV: for each k-step s, rebuild P A-frag from sc[s] C-frag via
        // quad shuffles, then accumulate over all 8 d-blocks.
        const int base = lane & ~3;
        const int src0 = base | (t4 >> 1);
        const int src2 = src0 + 2;
        const bool odd = (t4 & 1) != 0;
#pragma unroll
        for (int s = 0; s < 8; s++) {
            float v00 = __shfl_sync(0xffffffffu, sc[s][0], src0);
            float v01 = __shfl_sync(0xffffffffu, sc[s][1], src0);
            float w00 = __shfl_sync(0xffffffffu, sc[s][2], src0);
            float w01 = __shfl_sync(0xffffffffu, sc[s][3], src0);
            float v20 = __shfl_sync(0xffffffffu, sc[s][0], src2);
            float v21 = __shfl_sync(0xffffffffu, sc[s][1], src2);
            float w20 = __shfl_sync(0xffffffffu, sc[s][2], src2);
            float w21 = __shfl_sync(0xffffffffu, sc[s][3], src2);
            uint32_t pa[4];
            pa[0] = f2tf32(odd ? v01 : v00);
            pa[1] = f2tf32(odd ? w01 : w00);
            pa[2] = f2tf32(odd ? v21 : v20);
            pa[3] = f2tf32(odd ? w21 : w20);
#pragma unroll
            for (int nb = 0; nb < 8; nb++) {
                uint32_t b0 = __float_as_uint(Vt[nb * 8 + g][s * 8 + t4]);
                uint32_t b1 = __float_as_uint(Vt[nb * 8 + g][s * 8 + t4 + 4]);
                mma_tf32(of[nb], pa, b0, b1);
            }
        }
    }

    // Epilogue: normalize, write g_Xo[b, q, h*64 + d]
    const float il0 = 1.0f / l0;
    const float il1 = 1.0f / l1;
#pragma unroll
    for (int nb = 0; nb < 8; nb++) {
        float2 o0, o1;
        o0.x = of[nb][0] * il0; o0.y = of[nb][1] * il0;
        o1.x = of[nb][2] * il1; o1.y = of[nb][3] * il1;
        const int col = h * DKH + nb * 8 + t4 * 2;
        *(float2*)(g_Xo + (size_t)(b * S_LEN + r0) * DM + col) = o0;
        *(float2*)(g_Xo + (size_t)(b * S_LEN + r1) * DM + col) = o1;
    }
}

// ---------------------------------------------------------------------------
extern "C" void kernel_launch(void* const* d_in, const int* in_sizes, int n_in,
                              void* d_out, int out_size)
{
    const float* query = (const float*)d_in[0];
    const float* key   = (const float*)d_in[1];
    const float* value = (const float*)d_in[2];
    const int*   mask  = (const int*)  d_in[3];
    const float* Wq    = (const float*)d_in[4];
    const float* bq    = (const float*)d_in[5];
    const float* Wk    = (const float*)d_in[6];
    const float* bk    = (const float*)d_in[7];
    const float* Wv    = (const float*)d_in[8];
    const float* bv    = (const float*)d_in[9];
    const float* Wo    = (const float*)d_in[10];
    const float* bo    = (const float*)d_in[11];
    float* out = (float*)d_out;

    float *qp, *kp, *vp, *xo;
    cudaGetSymbolAddress((void**)&qp, g_Qp);
    cudaGetSymbolAddress((void**)&kp, g_Kp);
    cudaGetSymbolAddress((void**)&vp, g_Vp);
    cudaGetSymbolAddress((void**)&xo, g_Xo);

    // Q projection: [4096,1024] @ [1024,1024] + bq  (128x128 tiles)
    gemm128_bias_kernel<<<dim3(DM / 128, NTOK / 128), 256>>>(query, Wq, bq, qp, NTOK, DM, DM);
    // K/V projections: [4096,1024] @ [1024,64]
    gemm_bias_kernel<<<dim3(DKH / 64, NTOK / 64), 256>>>(key, Wk, bk, kp, NTOK, DKH, DM);
    gemm_bias_kernel<<<dim3(DKH / 64, NTOK / 64), 256>>>(value, Wv, bv, vp, NTOK, DKH, DM);
    // Fused masked MQA attention (tf32 tensor cores)
    attn_mma_kernel<<<dim3(S_LEN / 64, NH, BATCH), 128>>>(mask);
    // Output projection
    gemm128_bias_kernel<<<dim3(DM / 128, NTOK / 128), 256>>>(xo, Wo, bo, out, NTOK, DM, DM);
}

// round 9
// speedup vs baseline: 1.7270x; 1.0563x over previous
#include <cuda_runtime.h>
#include <cstdint>

// Problem constants
#define S_LEN  2048
#define DM     1024
#define NH     16
#define DKH    64
#define BATCH  2
#define NTOK   (BATCH * S_LEN)   // 4096

// Scratch (allocation-free rule: __device__ globals)
__device__ float g_Qp[(size_t)NTOK * DM];    // projected Q  [B*S, D]
__device__ float g_Kp[(size_t)NTOK * DKH];   // projected K  [B*S, d_k]
__device__ float g_Vp[(size_t)NTOK * DKH];   // projected V  [B*S, d_k]
__device__ float g_Xo[(size_t)NTOK * DM];    // attention out [B*S, D]

// ---------------------------------------------------------------------------
// helpers
// ---------------------------------------------------------------------------
__device__ __forceinline__ uint32_t f2tf32(float x) {
    uint32_t r;
    asm("cvt.rna.tf32.f32 %0, %1;" : "=r"(r) : "f"(x));
    return r;
}
__device__ __forceinline__ float tf32r(float x) {
    return __uint_as_float(f2tf32(x));
}

// exp2 on the FMA pipe (no MUFU): round-to-nearest split + deg-5 Taylor on
// [-0.5, 0.5] (rel err ~2.4e-6), exponent via bit-splice.
__device__ __forceinline__ float exp2_fast(float x) {
    x = fmaxf(x, -126.0f);
    int   i = __float2int_rn(x);
    float f = x - (float)i;
    float p = 0.0013333558f;
    p = fmaf(p, f, 0.0096181291f);
    p = fmaf(p, f, 0.0555041087f);
    p = fmaf(p, f, 0.2402265070f);
    p = fmaf(p, f, 0.6931471806f);
    p = fmaf(p, f, 1.0f);
    return p * __int_as_float((i + 127) << 23);
}

__device__ __forceinline__ void mma_tf32(float c[4], const uint32_t a[4],
                                         uint32_t b0, uint32_t b1) {
    asm volatile(
        "mma.sync.aligned.m16n8k8.row.col.f32.tf32.tf32.f32 "
        "{%0,%1,%2,%3}, {%4,%5,%6,%7}, {%8,%9}, {%0,%1,%2,%3};\n"
        : "+f"(c[0]), "+f"(c[1]), "+f"(c[2]), "+f"(c[3])
        : "r"(a[0]), "r"(a[1]), "r"(a[2]), "r"(a[3]), "r"(b0), "r"(b1));
}

// ---------------------------------------------------------------------------
// Small GEMM (K/V projections, N=64): unchanged FFMA path.
// ---------------------------------------------------------------------------
__global__ __launch_bounds__(256) void gemm_bias_kernel(
    const float* __restrict__ A, const float* __restrict__ B,
    const float* __restrict__ bias, float* __restrict__ C,
    int M, int N, int K)
{
    __shared__ float As[16][68];
    __shared__ float Bs[16][68];

    const int tid = threadIdx.x;
    const int tx  = tid & 15;
    const int ty  = tid >> 4;
    const int m0  = blockIdx.y << 6;
    const int n0  = blockIdx.x << 6;

    const int ar = tid >> 2;
    const int ak = (tid & 3) << 2;
    const int br = tid >> 4;
    const int bn = (tid & 15) << 2;

    float acc[4][4];
#pragma unroll
    for (int i = 0; i < 4; i++)
#pragma unroll
        for (int j = 0; j < 4; j++) acc[i][j] = 0.0f;

    for (int k0 = 0; k0 < K; k0 += 16) {
        float4 a = *(const float4*)(A + (size_t)(m0 + ar) * K + (k0 + ak));
        float4 b = *(const float4*)(B + (size_t)(k0 + br) * N + (n0 + bn));
        As[ak + 0][ar] = a.x;
        As[ak + 1][ar] = a.y;
        As[ak + 2][ar] = a.z;
        As[ak + 3][ar] = a.w;
        *(float4*)&Bs[br][bn] = b;
        __syncthreads();

#pragma unroll
        for (int kk = 0; kk < 16; kk++) {
            float4 av = *(const float4*)&As[kk][ty << 2];
            float4 bv = *(const float4*)&Bs[kk][tx << 2];
            acc[0][0] += av.x * bv.x; acc[0][1] += av.x * bv.y;
            acc[0][2] += av.x * bv.z; acc[0][3] += av.x * bv.w;
            acc[1][0] += av.y * bv.x; acc[1][1] += av.y * bv.y;
            acc[1][2] += av.y * bv.z; acc[1][3] += av.y * bv.w;
            acc[2][0] += av.z * bv.x; acc[2][1] += av.z * bv.y;
            acc[2][2] += av.z * bv.z; acc[2][3] += av.z * bv.w;
            acc[3][0] += av.w * bv.x; acc[3][1] += av.w * bv.y;
            acc[3][2] += av.w * bv.z; acc[3][3] += av.w * bv.w;
        }
        __syncthreads();
    }

    float4 bb = *(const float4*)(bias + n0 + (tx << 2));
#pragma unroll
    for (int i = 0; i < 4; i++) {
        float4 o;
        o.x = acc[i][0] + bb.x;
        o.y = acc[i][1] + bb.y;
        o.z = acc[i][2] + bb.z;
        o.w = acc[i][3] + bb.w;
        *(float4*)(C + (size_t)(m0 + (ty << 2) + i) * N + n0 + (tx << 2)) = o;
    }
}

// ---------------------------------------------------------------------------
// Split-tf32 (3-mma) GEMM for Q and O projections. Near-fp32 accuracy:
// v = hi + lo (tf32 each, 22 effective mantissa bits); C = AhBh + AhBl + AlBh.
// 256 thr / 8 warps; block tile 128x128, BK=16; warp tile m32 x n64.
// Smem pad 136 -> fragment LDS bank = (8*t4 + g) % 32, conflict-free.
// ---------------------------------------------------------------------------
#define GPAD 136

__global__ __launch_bounds__(256, 2) void gemm_mma_bias_kernel(
    const float* __restrict__ A, const float* __restrict__ B,
    const float* __restrict__ bias, float* __restrict__ C,
    int M, int N, int K)
{
    __shared__ float Ah[16][GPAD], Al[16][GPAD];
    __shared__ float Bh[16][GPAD], Bl[16][GPAD];

    const int tid  = threadIdx.x;
    const int lane = tid & 31;
    const int warp = tid >> 5;
    const int g    = lane >> 2;
    const int t4   = lane & 3;
    const int wm   = warp >> 1;        // 0..3  (m sub-tile)
    const int wn   = warp & 1;         // 0..1  (n sub-tile)
    const int m0   = blockIdx.y << 7;
    const int n0   = blockIdx.x << 7;

    const int ar = tid >> 1;           // 0..127
    const int ak = (tid & 1) << 3;     // 0 or 8
    const int br = tid >> 4;           // 0..15
    const int bn = (tid & 15) << 3;    // 0..120

    float acc[2][8][4];
#pragma unroll
    for (int f = 0; f < 2; f++)
#pragma unroll
        for (int j = 0; j < 8; j++)
#pragma unroll
            for (int r = 0; r < 4; r++) acc[f][j][r] = 0.0f;

    for (int k0 = 0; k0 < K; k0 += 16) {
        // ---- load + split tiles ----
        {
            float av[8];
            *(float4*)&av[0] = *(const float4*)(A + (size_t)(m0 + ar) * K + (k0 + ak));
            *(float4*)&av[4] = *(const float4*)(A + (size_t)(m0 + ar) * K + (k0 + ak + 4));
#pragma unroll
            for (int i = 0; i < 8; i++) {
                float hi = tf32r(av[i]);
                Ah[ak + i][ar] = hi;
                Al[ak + i][ar] = tf32r(av[i] - hi);
            }
            float bv[8];
            *(float4*)&bv[0] = *(const float4*)(B + (size_t)(k0 + br) * N + (n0 + bn));
            *(float4*)&bv[4] = *(const float4*)(B + (size_t)(k0 + br) * N + (n0 + bn + 4));
            float bh[8], bl[8];
#pragma unroll
            for (int i = 0; i < 8; i++) {
                bh[i] = tf32r(bv[i]);
                bl[i] = tf32r(bv[i] - bh[i]);
            }
            *(float4*)&Bh[br][bn]     = *(float4*)&bh[0];
            *(float4*)&Bh[br][bn + 4] = *(float4*)&bh[4];
            *(float4*)&Bl[br][bn]     = *(float4*)&bl[0];
            *(float4*)&Bl[br][bn + 4] = *(float4*)&bl[4];
        }
        __syncthreads();

#pragma unroll
        for (int ks = 0; ks < 16; ks += 8) {
            // A fragments (hi+lo) for this warp's two m16 tiles
            uint32_t ah[2][4], al[2][4];
#pragma unroll
            for (int f = 0; f < 2; f++) {
                const int m = wm * 32 + f * 16;
                ah[f][0] = __float_as_uint(Ah[ks + t4][m + g]);
                ah[f][1] = __float_as_uint(Ah[ks + t4][m + g + 8]);
                ah[f][2] = __float_as_uint(Ah[ks + t4 + 4][m + g]);
                ah[f][3] = __float_as_uint(Ah[ks + t4 + 4][m + g + 8]);
                al[f][0] = __float_as_uint(Al[ks + t4][m + g]);
                al[f][1] = __float_as_uint(Al[ks + t4][m + g + 8]);
                al[f][2] = __float_as_uint(Al[ks + t4 + 4][m + g]);
                al[f][3] = __float_as_uint(Al[ks + t4 + 4][m + g + 8]);
            }
#pragma unroll
            for (int j = 0; j < 8; j++) {
                const int n = wn * 64 + j * 8 + g;
                uint32_t bh0 = __float_as_uint(Bh[ks + t4][n]);
                uint32_t bh1 = __float_as_uint(Bh[ks + t4 + 4][n]);
                uint32_t bl0 = __float_as_uint(Bl[ks + t4][n]);
                uint32_t bl1 = __float_as_uint(Bl[ks + t4 + 4][n]);
#pragma unroll
                for (int f = 0; f < 2; f++) {
                    mma_tf32(acc[f][j], ah[f], bh0, bh1);
                    mma_tf32(acc[f][j], ah[f], bl0, bl1);
                    mma_tf32(acc[f][j], al[f], bh0, bh1);
                }
            }
        }
        __syncthreads();
    }

    // ---- epilogue: bias + store (C-frag: c0/c1 row g cols 2t4,2t4+1; c2/c3 row g+8)
#pragma unroll
    for (int j = 0; j < 8; j++) {
        const int n = n0 + wn * 64 + j * 8 + t4 * 2;
        float2 bs = *(const float2*)(bias + n);
#pragma unroll
        for (int f = 0; f < 2; f++) {
            const int r = m0 + wm * 32 + f * 16 + g;
            float2 o0, o1;
            o0.x = acc[f][j][0] + bs.x; o0.y = acc[f][j][1] + bs.y;
            o1.x = acc[f][j][2] + bs.x; o1.y = acc[f][j][3] + bs.y;
            *(float2*)(C + (size_t)r * N + n)       = o0;
            *(float2*)(C + (size_t)(r + 8) * N + n) = o1;
        }
    }
}

// ---------------------------------------------------------------------------
// Fused masked MQA attention — tf32 mma.sync tensor cores (unchanged from R8).
// ---------------------------------------------------------------------------
#define KPAD 68

__global__ __launch_bounds__(128, 3) void attn_mma_kernel(const int* __restrict__ mask)
{
    __shared__ float Kv[64][KPAD];   // Kv[kseq][d]
    __shared__ float Vt[64][KPAD];   // Vt[d][kseq]

    const int tid  = threadIdx.x;
    const int lane = tid & 31;
    const int warp = tid >> 5;
    const int g    = lane >> 2;
    const int t4   = lane & 3;
    const int q0   = blockIdx.x << 6;
    const int h    = blockIdx.y;
    const int b    = blockIdx.z;

    const float* Qb = g_Qp + (size_t)b * S_LEN * DM + h * DKH;
    const float* Kb = g_Kp + (size_t)b * S_LEN * DKH;
    const float* Vb = g_Vp + (size_t)b * S_LEN * DKH;
    const int*   Mb = mask + (size_t)b * S_LEN * S_LEN;

    const int r0 = q0 + warp * 16 + g;
    const int r1 = r0 + 8;
    const float qsc = 0.125f * 1.4426950408889634f;
    uint32_t qa[8][4];
#pragma unroll
    for (int s = 0; s < 8; s++) {
        qa[s][0] = f2tf32(Qb[(size_t)r0 * DM + s * 8 + t4]     * qsc);
        qa[s][1] = f2tf32(Qb[(size_t)r1 * DM + s * 8 + t4]     * qsc);
        qa[s][2] = f2tf32(Qb[(size_t)r0 * DM + s * 8 + t4 + 4] * qsc);
        qa[s][3] = f2tf32(Qb[(size_t)r1 * DM + s * 8 + t4 + 4] * qsc);
    }

    float m0 = -1e30f, m1 = -1e30f, l0 = 0.0f, l1 = 0.0f;
    float of[8][4];
#pragma unroll
    for (int nb = 0; nb < 8; nb++)
#pragma unroll
        for (int r = 0; r < 4; r++) of[nb][r] = 0.0f;

    for (int k0 = 0; k0 < S_LEN; k0 += 64) {
        __syncthreads();
        {
            const int r  = tid >> 1;
            const int cb = (tid & 1) * 8;
#pragma unroll
            for (int i = 0; i < 8; i++) {
                const int c = (cb + i) * 4;
                float4 kv = *(const float4*)(Kb + (size_t)(k0 + r) * DKH + c);
                Kv[r][c + 0] = tf32r(kv.x);
                Kv[r][c + 1] = tf32r(kv.y);
                Kv[r][c + 2] = tf32r(kv.z);
                Kv[r][c + 3] = tf32r(kv.w);
                float4 vv = *(const float4*)(Vb + (size_t)(k0 + r) * DKH + c);
                Vt[c + 0][r] = tf32r(vv.x);
                Vt[c + 1][r] = tf32r(vv.y);
                Vt[c + 2][r] = tf32r(vv.z);
                Vt[c + 3][r] = tf32r(vv.w);
            }
        }
        __syncthreads();

        float sc[8][4];
#pragma unroll
        for (int j = 0; j < 8; j++) {
            sc[j][0] = sc[j][1] = sc[j][2] = sc[j][3] = 0.0f;
#pragma unroll
            for (int s = 0; s < 8; s++) {
                uint32_t b0 = __float_as_uint(Kv[j * 8 + g][s * 8 + t4]);
                uint32_t b1 = __float_as_uint(Kv[j * 8 + g][s * 8 + t4 + 4]);
                mma_tf32(sc[j], qa[s], b0, b1);
            }
        }

#pragma unroll
        for (int j = 0; j < 8; j++) {
            const int c0 = k0 + j * 8 + t4 * 2;
            int2 mA = *(const int2*)(Mb + (size_t)r0 * S_LEN + c0);
            int2 mB = *(const int2*)(Mb + (size_t)r1 * S_LEN + c0);
            sc[j][0] = mA.x ? sc[j][0] : -1.0e9f;
            sc[j][1] = mA.y ? sc[j][1] : -1.0e9f;
            sc[j][2] = mB.x ? sc[j][2] : -1.0e9f;
            sc[j][3] = mB.y ? sc[j][3] : -1.0e9f;
        }

        float mx0 = -1e30f, mx1 = -1e30f;
#pragma unroll
        for (int j = 0; j < 8; j++) {
            mx0 = fmaxf(mx0, fmaxf(sc[j][0], sc[j][1]));
            mx1 = fmaxf(mx1, fmaxf(sc[j][2], sc[j][3]));
        }
        mx0 = fmaxf(mx0, __shfl_xor_sync(0xffffffffu, mx0, 1));
        mx0 = fmaxf(mx0, __shfl_xor_sync(0xffffffffu, mx0, 2));
        mx1 = fmaxf(mx1, __shfl_xor_sync(0xffffffffu, mx1, 1));
        mx1 = fmaxf(mx1, __shfl_xor_sync(0xffffffffu, mx1, 2));

        const float mn0 = fmaxf(m0, mx0);
        const float mn1 = fmaxf(m1, mx1);
        const float corr0 = exp2_fast(m0 - mn0);
        const float corr1 = exp2_fast(m1 - mn1);
        m0 = mn0; m1 = mn1;

        float rs0 = 0.0f, rs1 = 0.0f;
#pragma unroll
        for (int j = 0; j < 8; j++) {
            sc[j][0] = exp2_fast(sc[j][0] - m0);
            sc[j][1] = exp2_fast(sc[j][1] - m0);
            sc[j][2] = exp2_fast(sc[j][2] - m1);
            sc[j][3] = exp2_fast(sc[j][3] - m1);
            rs0 += sc[j][0] + sc[j][1];
            rs1 += sc[j][2] + sc[j][3];
        }
        rs0 += __shfl_xor_sync(0xffffffffu, rs0, 1);
        rs0 += __shfl_xor_sync(0xffffffffu, rs0, 2);
        rs1 += __shfl_xor_sync(0xffffffffu, rs1, 1);
        rs1 += __shfl_xor_sync(0xffffffffu, rs1, 2);
        l0 = l0 * corr0 + rs0;
        l1 = l1 * corr1 + rs1;

#pragma unroll
        for (int nb = 0; nb < 8; nb++) {
            of[nb][0] *= corr0; of[nb][1] *= corr0;
            of[nb][2] *= corr1; of[nb][3] *= corr1;
        }

        const int base = lane & ~3;
        const int src0 = base | (t4 >> 1);
        const int src2 = src0 + 2;
        const bool odd = (t4 & 1) != 0;
#pragma unroll
        for (int s = 0; s < 8; s++) {
            float v00 = __shfl_sync(0xffffffffu, sc[s][0], src0);
            float v01 = __shfl_sync(0xffffffffu, sc[s][1], src0);
            float w00 = __shfl_sync(0xffffffffu, sc[s][2], src0);
            float w01 = __shfl_sync(0xffffffffu, sc[s][3], src0);
            float v20 = __shfl_sync(0xffffffffu, sc[s][0], src2);
            float v21 = __shfl_sync(0xffffffffu, sc[s][1], src2);
            float w20 = __shfl_sync(0xffffffffu, sc[s][2], src2);
            float w21 = __shfl_sync(0xffffffffu, sc[s][3], src2);
            uint32_t pa[4];
            pa[0] = f2tf32(odd ? v01 : v00);
            pa[1] = f2tf32(odd ? w01 : w00);
            pa[2] = f2tf32(odd ? v21 : v20);
            pa[3] = f2tf32(odd ? w21 : w20);
#pragma unroll
            for (int nb = 0; nb < 8; nb++) {
                uint32_t b0 = __float_as_uint(Vt[nb * 8 + g][s * 8 + t4]);
                uint32_t b1 = __float_as_uint(Vt[nb * 8 + g][s * 8 + t4 + 4]);
                mma_tf32(of[nb], pa, b0, b1);
            }
        }
    }

    const float il0 = 1.0f / l0;
    const float il1 = 1.0f / l1;
#pragma unroll
    for (int nb = 0; nb < 8; nb++) {
        float2 o0, o1;
        o0.x = of[nb][0] * il0; o0.y = of[nb][1] * il0;
        o1.x = of[nb][2] * il1; o1.y = of[nb][3] * il1;
        const int col = h * DKH + nb * 8 + t4 * 2;
        *(float2*)(g_Xo + (size_t)(b * S_LEN + r0) * DM + col) = o0;
        *(float2*)(g_Xo + (size_t)(b * S_LEN + r1) * DM + col) = o1;
    }
}

// ---------------------------------------------------------------------------
extern "C" void kernel_launch(void* const* d_in, const int* in_sizes, int n_in,
                              void* d_out, int out_size)
{
    const float* query = (const float*)d_in[0];
    const float* key   = (const float*)d_in[1];
    const float* value = (const float*)d_in[2];
    const int*   mask  = (const int*)  d_in[3];
    const float* Wq    = (const float*)d_in[4];
    const float* bq    = (const float*)d_in[5];
    const float* Wk    = (const float*)d_in[6];
    const float* bk    = (const float*)d_in[7];
    const float* Wv    = (const float*)d_in[8];
    const float* bv    = (const float*)d_in[9];
    const float* Wo    = (const float*)d_in[10];
    const float* bo    = (const float*)d_in[11];
    float* out = (float*)d_out;

    float *qp, *kp, *vp, *xo;
    cudaGetSymbolAddress((void**)&qp, g_Qp);
    cudaGetSymbolAddress((void**)&kp, g_Kp);
    cudaGetSymbolAddress((void**)&vp, g_Vp);
    cudaGetSymbolAddress((void**)&xo, g_Xo);

    // Q projection: [4096,1024] @ [1024,1024] + bq  (split-tf32 tensor GEMM)
    gemm_mma_bias_kernel<<<dim3(DM / 128, NTOK / 128), 256>>>(query, Wq, bq, qp, NTOK, DM, DM);
    // K/V projections: [4096,1024] @ [1024,64]  (FFMA)
    gemm_bias_kernel<<<dim3(DKH / 64, NTOK / 64), 256>>>(key, Wk, bk, kp, NTOK, DKH, DM);
    gemm_bias_kernel<<<dim3(DKH / 64, NTOK / 64), 256>>>(value, Wv, bv, vp, NTOK, DKH, DM);
    // Fused masked MQA attention (tf32 tensor cores)
    attn_mma_kernel<<<dim3(S_LEN / 64, NH, BATCH), 128>>>(mask);
    // Output projection (split-tf32 tensor GEMM)
    gemm_mma_bias_kernel<<<dim3(DM / 128, NTOK / 128), 256>>>(xo, Wo, bo, out, NTOK, DM, DM);
}

// round 13
// speedup vs baseline: 2.1444x; 1.2417x over previous
#include <cuda_runtime.h>
#include <cstdint>

// Problem constants
#define S_LEN  2048
#define DM     1024
#define NH     16
#define DKH    64
#define BATCH  2
#define NTOK   (BATCH * S_LEN)   // 4096

// Scratch (allocation-free rule: __device__ globals)
__device__ float g_Qp[(size_t)NTOK * DM];    // projected Q  [B*S, D]
__device__ float g_Kp[(size_t)NTOK * DKH];   // projected K  [B*S, d_k]
__device__ float g_Vp[(size_t)NTOK * DKH];   // projected V  [B*S, d_k]
__device__ float g_Xo[(size_t)NTOK * DM];    // attention out [B*S, D]

// ---------------------------------------------------------------------------
// helpers
// ---------------------------------------------------------------------------
__device__ __forceinline__ uint32_t f2tf32(float x) {
    uint32_t r;
    asm("cvt.rna.tf32.f32 %0, %1;" : "=r"(r) : "f"(x));
    return r;
}
__device__ __forceinline__ float tf32r(float x) {
    return __uint_as_float(f2tf32(x));
}

// exp2 on the FMA pipe (no MUFU): round-to-nearest split + deg-5 Taylor on
// [-0.5, 0.5] (rel err ~2.4e-6), exponent via bit-splice.
__device__ __forceinline__ float exp2_fast(float x) {
    x = fmaxf(x, -126.0f);
    int   i = __float2int_rn(x);
    float f = x - (float)i;
    float p = 0.0013333558f;
    p = fmaf(p, f, 0.0096181291f);
    p = fmaf(p, f, 0.0555041087f);
    p = fmaf(p, f, 0.2402265070f);
    p = fmaf(p, f, 0.6931471806f);
    p = fmaf(p, f, 1.0f);
    return p * __int_as_float((i + 127) << 23);
}

__device__ __forceinline__ void mma_tf32(float c[4], const uint32_t a[4],
                                         uint32_t b0, uint32_t b1) {
    asm volatile(
        "mma.sync.aligned.m16n8k8.row.col.f32.tf32.tf32.f32 "
        "{%0,%1,%2,%3}, {%4,%5,%6,%7}, {%8,%9}, {%0,%1,%2,%3};\n"
        : "+f"(c[0]), "+f"(c[1]), "+f"(c[2]), "+f"(c[3])
        : "r"(a[0]), "r"(a[1]), "r"(a[2]), "r"(a[3]), "r"(b0), "r"(b1));
}

// ---------------------------------------------------------------------------
// Small GEMM (K/V projections, N=64): FFMA path (unchanged).
// ---------------------------------------------------------------------------
__global__ __launch_bounds__(256) void gemm_bias_kernel(
    const float* __restrict__ A, const float* __restrict__ B,
    const float* __restrict__ bias, float* __restrict__ C,
    int M, int N, int K)
{
    __shared__ float As[16][68];
    __shared__ float Bs[16][68];

    const int tid = threadIdx.x;
    const int tx  = tid & 15;
    const int ty  = tid >> 4;
    const int m0  = blockIdx.y << 6;
    const int n0  = blockIdx.x << 6;

    const int ar = tid >> 2;
    const int ak = (tid & 3) << 2;
    const int br = tid >> 4;
    const int bn = (tid & 15) << 2;

    float acc[4][4];
#pragma unroll
    for (int i = 0; i < 4; i++)
#pragma unroll
        for (int j = 0; j < 4; j++) acc[i][j] = 0.0f;

    for (int k0 = 0; k0 < K; k0 += 16) {
        float4 a = *(const float4*)(A + (size_t)(m0 + ar) * K + (k0 + ak));
        float4 b = *(const float4*)(B + (size_t)(k0 + br) * N + (n0 + bn));
        As[ak + 0][ar] = a.x;
        As[ak + 1][ar] = a.y;
        As[ak + 2][ar] = a.z;
        As[ak + 3][ar] = a.w;
        *(float4*)&Bs[br][bn] = b;
        __syncthreads();

#pragma unroll
        for (int kk = 0; kk < 16; kk++) {
            float4 av = *(const float4*)&As[kk][ty << 2];
            float4 bv = *(const float4*)&Bs[kk][tx << 2];
            acc[0][0] += av.x * bv.x; acc[0][1] += av.x * bv.y;
            acc[0][2] += av.x * bv.z; acc[0][3] += av.x * bv.w;
            acc[1][0] += av.y * bv.x; acc[1][1] += av.y * bv.y;
            acc[1][2] += av.y * bv.z; acc[1][3] += av.y * bv.w;
            acc[2][0] += av.z * bv.x; acc[2][1] += av.z * bv.y;
            acc[2][2] += av.z * bv.z; acc[2][3] += av.z * bv.w;
            acc[3][0] += av.w * bv.x; acc[3][1] += av.w * bv.y;
            acc[3][2] += av.w * bv.z; acc[3][3] += av.w * bv.w;
        }
        __syncthreads();
    }

    float4 bb = *(const float4*)(bias + n0 + (tx << 2));
#pragma unroll
    for (int i = 0; i < 4; i++) {
        float4 o;
        o.x = acc[i][0] + bb.x;
        o.y = acc[i][1] + bb.y;
        o.z = acc[i][2] + bb.z;
        o.w = acc[i][3] + bb.w;
        *(float4*)(C + (size_t)(m0 + (ty << 2) + i) * N + n0 + (tx << 2)) = o;
    }
}

// ---------------------------------------------------------------------------
// Split-tf32 (3-mma) GEMM for Q and O projections (unchanged from R9).
// ---------------------------------------------------------------------------
#define GPAD 136

__global__ __launch_bounds__(256, 2) void gemm_mma_bias_kernel(
    const float* __restrict__ A, const float* __restrict__ B,
    const float* __restrict__ bias, float* __restrict__ C,
    int M, int N, int K)
{
    __shared__ float Ah[16][GPAD], Al[16][GPAD];
    __shared__ float Bh[16][GPAD], Bl[16][GPAD];

    const int tid  = threadIdx.x;
    const int lane = tid & 31;
    const int warp = tid >> 5;
    const int g    = lane >> 2;
    const int t4   = lane & 3;
    const int wm   = warp >> 1;
    const int wn   = warp & 1;
    const int m0   = blockIdx.y << 7;
    const int n0   = blockIdx.x << 7;

    const int ar = tid >> 1;
    const int ak = (tid & 1) << 3;
    const int br = tid >> 4;
    const int bn = (tid & 15) << 3;

    float acc[2][8][4];
#pragma unroll
    for (int f = 0; f < 2; f++)
#pragma unroll
        for (int j = 0; j < 8; j++)
#pragma unroll
            for (int r = 0; r < 4; r++) acc[f][j][r] = 0.0f;

    for (int k0 = 0; k0 < K; k0 += 16) {
        {
            float av[8];
            *(float4*)&av[0] = *(const float4*)(A + (size_t)(m0 + ar) * K + (k0 + ak));
            *(float4*)&av[4] = *(const float4*)(A + (size_t)(m0 + ar) * K + (k0 + ak + 4));
#pragma unroll
            for (int i = 0; i < 8; i++) {
                float hi = tf32r(av[i]);
                Ah[ak + i][ar] = hi;
                Al[ak + i][ar] = tf32r(av[i] - hi);
            }
            float bv[8];
            *(float4*)&bv[0] = *(const float4*)(B + (size_t)(k0 + br) * N + (n0 + bn));
            *(float4*)&bv[4] = *(const float4*)(B + (size_t)(k0 + br) * N + (n0 + bn + 4));
            float bh[8], bl[8];
#pragma unroll
            for (int i = 0; i < 8; i++) {
                bh[i] = tf32r(bv[i]);
                bl[i] = tf32r(bv[i] - bh[i]);
            }
            *(float4*)&Bh[br][bn]     = *(float4*)&bh[0];
            *(float4*)&Bh[br][bn + 4] = *(float4*)&bh[4];
            *(float4*)&Bl[br][bn]     = *(float4*)&bl[0];
            *(float4*)&Bl[br][bn + 4] = *(float4*)&bl[4];
        }
        __syncthreads();

#pragma unroll
        for (int ks = 0; ks < 16; ks += 8) {
            uint32_t ah[2][4], al[2][4];
#pragma unroll
            for (int f = 0; f < 2; f++) {
                const int m = wm * 32 + f * 16;
                ah[f][0] = __float_as_uint(Ah[ks + t4][m + g]);
                ah[f][1] = __float_as_uint(Ah[ks + t4][m + g + 8]);
                ah[f][2] = __float_as_uint(Ah[ks + t4 + 4][m + g]);
                ah[f][3] = __float_as_uint(Ah[ks + t4 + 4][m + g + 8]);
                al[f][0] = __float_as_uint(Al[ks + t4][m + g]);
                al[f][1] = __float_as_uint(Al[ks + t4][m + g + 8]);
                al[f][2] = __float_as_uint(Al[ks + t4 + 4][m + g]);
                al[f][3] = __float_as_uint(Al[ks + t4 + 4][m + g + 8]);
            }
#pragma unroll
            for (int j = 0; j < 8; j++) {
                const int n = wn * 64 + j * 8 + g;
                uint32_t bh0 = __float_as_uint(Bh[ks + t4][n]);
                uint32_t bh1 = __float_as_uint(Bh[ks + t4 + 4][n]);
                uint32_t bl0 = __float_as_uint(Bl[ks + t4][n]);
                uint32_t bl1 = __float_as_uint(Bl[ks + t4 + 4][n]);
#pragma unroll
                for (int f = 0; f < 2; f++) {
                    mma_tf32(acc[f][j], ah[f], bh0, bh1);
                    mma_tf32(acc[f][j], ah[f], bl0, bl1);
                    mma_tf32(acc[f][j], al[f], bh0, bh1);
                }
            }
        }
        __syncthreads();
    }

#pragma unroll
    for (int j = 0; j < 8; j++) {
        const int n = n0 + wn * 64 + j * 8 + t4 * 2;
        float2 bs = *(const float2*)(bias + n);
#pragma unroll
        for (int f = 0; f < 2; f++) {
            const int r = m0 + wm * 32 + f * 16 + g;
            float2 o0, o1;
            o0.x = acc[f][j][0] + bs.x; o0.y = acc[f][j][1] + bs.y;
            o1.x = acc[f][j][2] + bs.x; o1.y = acc[f][j][3] + bs.y;
            *(float2*)(C + (size_t)r * N + n)       = o0;
            *(float2*)(C + (size_t)(r + 8) * N + n) = o1;
        }
    }
}

// ---------------------------------------------------------------------------
// Fused masked MQA attention — tf32 mma.sync, warp tile m32 (f=0,1), KT=32.
// Each B-fragment LDS pair feeds TWO MMAs (halves LDS per MAC vs m16).
// K natural [kseq][d] pad 68 (score B-frag bank 4g+8s+t4 conflict-free),
// V natural [kseq][d] pad 72 (PV B-frag bank 8*t4+g conflict-free, NO
// transpose store). Both tiles stored with aligned float4 STS.
// ---------------------------------------------------------------------------
#define KT2   32
#define KVPAD 68   // == 4 (mod 32)
#define VPAD  72   // == 8 (mod 32)

__global__ __launch_bounds__(128, 2) void attn_mma_kernel(const int* __restrict__ mask)
{
    __shared__ float Kv[KT2][KVPAD];   // Kv[kseq][d]
    __shared__ float Vs[KT2][VPAD];    // Vs[kseq][d]

    const int tid  = threadIdx.x;
    const int lane = tid & 31;
    const int warp = tid >> 5;
    const int g    = lane >> 2;
    const int t4   = lane & 3;
    const int q0   = blockIdx.x << 7;       // 128 q-rows per block
    const int h    = blockIdx.y;
    const int b    = blockIdx.z;

    const float* Qb = g_Qp + (size_t)b * S_LEN * DM + h * DKH;
    const float* Kb = g_Kp + (size_t)b * S_LEN * DKH;
    const float* Vb = g_Vp + (size_t)b * S_LEN * DKH;
    const int*   Mb = mask + (size_t)b * S_LEN * S_LEN;

    // Warp owns q-rows [q0+warp*32, q0+warp*32+32). f in {0,1} selects m16 half.
    // Rows for frag f: rA = rbase + f*16 + g, rB = rA + 8.
    const int rbase = q0 + warp * 32;
    const float qsc = 0.125f * 1.4426950408889634f;   // fold 1/8 and log2(e)

    uint32_t qa[2][8][4];
#pragma unroll
    for (int f = 0; f < 2; f++) {
        const int rA = rbase + f * 16 + g;
        const int rB = rA + 8;
#pragma unroll
        for (int s = 0; s < 8; s++) {
            qa[f][s][0] = f2tf32(Qb[(size_t)rA * DM + s * 8 + t4]     * qsc);
            qa[f][s][1] = f2tf32(Qb[(size_t)rB * DM + s * 8 + t4]     * qsc);
            qa[f][s][2] = f2tf32(Qb[(size_t)rA * DM + s * 8 + t4 + 4] * qsc);
            qa[f][s][3] = f2tf32(Qb[(size_t)rB * DM + s * 8 + t4 + 4] * qsc);
        }
    }

    float m_[2][2], l_[2][2];
#pragma unroll
    for (int f = 0; f < 2; f++) {
        m_[f][0] = -1e30f; m_[f][1] = -1e30f;
        l_[f][0] = 0.0f;   l_[f][1] = 0.0f;
    }
    float of[2][8][4];
#pragma unroll
    for (int f = 0; f < 2; f++)
#pragma unroll
        for (int nb = 0; nb < 8; nb++)
#pragma unroll
            for (int r = 0; r < 4; r++) of[f][nb][r] = 0.0f;

    for (int k0 = 0; k0 < S_LEN; k0 += KT2) {
        __syncthreads();
        // Load K and V tiles, natural layout, tf32-rounded, float4 STS.
        {
            const int r  = tid >> 2;          // 0..31 (kseq row)
            const int cq = tid & 3;           // col-quad base
#pragma unroll
            for (int it = 0; it < 4; it++) {
                const int c = (cq + it * 4) << 2;   // 0..60
                float4 kv = *(const float4*)(Kb + (size_t)(k0 + r) * DKH + c);
                kv.x = tf32r(kv.x); kv.y = tf32r(kv.y);
                kv.z = tf32r(kv.z); kv.w = tf32r(kv.w);
                *(float4*)&Kv[r][c] = kv;
                float4 vv = *(const float4*)(Vb + (size_t)(k0 + r) * DKH + c);
                vv.x = tf32r(vv.x); vv.y = tf32r(vv.y);
                vv.z = tf32r(vv.z); vv.w = tf32r(vv.w);
                *(float4*)&Vs[r][c] = vv;
            }
        }
        __syncthreads();

        // Scores: sc[f][j] = m16x8 C-frag, cols k0+j*8..+7, j in 0..3
        float sc[2][4][4];
#pragma unroll
        for (int j = 0; j < 4; j++) {
#pragma unroll
            for (int f = 0; f < 2; f++)
                sc[f][j][0] = sc[f][j][1] = sc[f][j][2] = sc[f][j][3] = 0.0f;
#pragma unroll
            for (int s = 0; s < 8; s++) {
                uint32_t b0 = __float_as_uint(Kv[j * 8 + g][s * 8 + t4]);
                uint32_t b1 = __float_as_uint(Kv[j * 8 + g][s * 8 + t4 + 4]);
                mma_tf32(sc[0][j], qa[0][s], b0, b1);
                mma_tf32(sc[1][j], qa[1][s], b0, b1);
            }
        }

        // Mask + online softmax per f (base-2 domain).
#pragma unroll
        for (int f = 0; f < 2; f++) {
            const int rA = rbase + f * 16 + g;
            const int rB = rA + 8;
#pragma unroll
            for (int j = 0; j < 4; j++) {
                const int c0 = k0 + j * 8 + t4 * 2;
                int2 mA = *(const int2*)(Mb + (size_t)rA * S_LEN + c0);
                int2 mB = *(const int2*)(Mb + (size_t)rB * S_LEN + c0);
                sc[f][j][0] = mA.x ? sc[f][j][0] : -1.0e9f;
                sc[f][j][1] = mA.y ? sc[f][j][1] : -1.0e9f;
                sc[f][j][2] = mB.x ? sc[f][j][2] : -1.0e9f;
                sc[f][j][3] = mB.y ? sc[f][j][3] : -1.0e9f;
            }

            float mx0 = -1e30f, mx1 = -1e30f;
#pragma unroll
            for (int j = 0; j < 4; j++) {
                mx0 = fmaxf(mx0, fmaxf(sc[f][j][0], sc[f][j][1]));
                mx1 = fmaxf(mx1, fmaxf(sc[f][j][2], sc[f][j][3]));
            }
            mx0 = fmaxf(mx0, __shfl_xor_sync(0xffffffffu, mx0, 1));
            mx0 = fmaxf(mx0, __shfl_xor_sync(0xffffffffu, mx0, 2));
            mx1 = fmaxf(mx1, __shfl_xor_sync(0xffffffffu, mx1, 1));
            mx1 = fmaxf(mx1, __shfl_xor_sync(0xffffffffu, mx1, 2));

            const float mn0 = fmaxf(m_[f][0], mx0);
            const float mn1 = fmaxf(m_[f][1], mx1);
            const float corr0 = exp2_fast(m_[f][0] - mn0);
            const float corr1 = exp2_fast(m_[f][1] - mn1);
            m_[f][0] = mn0; m_[f][1] = mn1;

            float rs0 = 0.0f, rs1 = 0.0f;
#pragma unroll
            for (int j = 0; j < 4; j++) {
                sc[f][j][0] = exp2_fast(sc[f][j][0] - mn0);
                sc[f][j][1] = exp2_fast(sc[f][j][1] - mn0);
                sc[f][j][2] = exp2_fast(sc[f][j][2] - mn1);
                sc[f][j][3] = exp2_fast(sc[f][j][3] - mn1);
                rs0 += sc[f][j][0] + sc[f][j][1];
                rs1 += sc[f][j][2] + sc[f][j][3];
            }
            rs0 += __shfl_xor_sync(0xffffffffu, rs0, 1);
            rs0 += __shfl_xor_sync(0xffffffffu, rs0, 2);
            rs1 += __shfl_xor_sync(0xffffffffu, rs1, 1);
            rs1 += __shfl_xor_sync(0xffffffffu, rs1, 2);
            l_[f][0] = l_[f][0] * corr0 + rs0;
            l_[f][1] = l_[f][1] * corr1 + rs1;

#pragma unroll
            for (int nb = 0; nb < 8; nb++) {
                of[f][nb][0] *= corr0; of[f][nb][1] *= corr0;
                of[f][nb][2] *= corr1; of[f][nb][3] *= corr1;
            }
        }

        // PV: rebuild P A-frags per (f, s) via quad shuffles; each V B-frag
        // load pair feeds both f MMAs.
        const int base = lane & ~3;
        const int src0 = base | (t4 >> 1);
        const int src2 = src0 + 2;
        const bool odd = (t4 & 1) != 0;
#pragma unroll
        for (int s = 0; s < 4; s++) {
            uint32_t pa[2][4];
#pragma unroll
            for (int f = 0; f < 2; f++) {
                float v00 = __shfl_sync(0xffffffffu, sc[f][s][0], src0);
                float v01 = __shfl_sync(0xffffffffu, sc[f][s][1], src0);
                float w00 = __shfl_sync(0xffffffffu, sc[f][s][2], src0);
                float w01 = __shfl_sync(0xffffffffu, sc[f][s][3], src0);
                float v20 = __shfl_sync(0xffffffffu, sc[f][s][0], src2);
                float v21 = __shfl_sync(0xffffffffu, sc[f][s][1], src2);
                float w20 = __shfl_sync(0xffffffffu, sc[f][s][2], src2);
                float w21 = __shfl_sync(0xffffffffu, sc[f][s][3], src2);
                pa[f][0] = f2tf32(odd ? v01 : v00);
                pa[f][1] = f2tf32(odd ? w01 : w00);
                pa[f][2] = f2tf32(odd ? v21 : v20);
                pa[f][3] = f2tf32(odd ? w21 : w20);
            }
#pragma unroll
            for (int nb = 0; nb < 8; nb++) {
                uint32_t b0 = __float_as_uint(Vs[s * 8 + t4][nb * 8 + g]);
                uint32_t b1 = __float_as_uint(Vs[s * 8 + t4 + 4][nb * 8 + g]);
                mma_tf32(of[0][nb], pa[0], b0, b1);
                mma_tf32(of[1][nb], pa[1], b0, b1);
            }
        }
    }

    // Epilogue: normalize, write g_Xo[b, q, h*64 + d]
#pragma unroll
    for (int f = 0; f < 2; f++) {
        const int rA = rbase + f * 16 + g;
        const int rB = rA + 8;
        const float il0 = 1.0f / l_[f][0];
        const float il1 = 1.0f / l_[f][1];
#pragma unroll
        for (int nb = 0; nb < 8; nb++) {
            float2 o0, o1;
            o0.x = of[f][nb][0] * il0; o0.y = of[f][nb][1] * il0;
            o1.x = of[f][nb][2] * il1; o1.y = of[f][nb][3] * il1;
            const int col = h * DKH + nb * 8 + t4 * 2;
            *(float2*)(g_Xo + (size_t)(b * S_LEN + rA) * DM + col) = o0;
            *(float2*)(g_Xo + (size_t)(b * S_LEN + rB) * DM + col) = o1;
        }
    }
}

// ---------------------------------------------------------------------------
extern "C" void kernel_launch(void* const* d_in, const int* in_sizes, int n_in,
                              void* d_out, int out_size)
{
    const float* query = (const float*)d_in[0];
    const float* key   = (const float*)d_in[1];
    const float* value = (const float*)d_in[2];
    const int*   mask  = (const int*)  d_in[3];
    const float* Wq    = (const float*)d_in[4];
    const float* bq    = (const float*)d_in[5];
    const float* Wk    = (const float*)d_in[6];
    const float* bk    = (const float*)d_in[7];
    const float* Wv    = (const float*)d_in[8];
    const float* bv    = (const float*)d_in[9];
    const float* Wo    = (const float*)d_in[10];
    const float* bo    = (const float*)d_in[11];
    float* out = (float*)d_out;

    float *qp, *kp, *vp, *xo;
    cudaGetSymbolAddress((void**)&qp, g_Qp);
    cudaGetSymbolAddress((void**)&kp, g_Kp);
    cudaGetSymbolAddress((void**)&vp, g_Vp);
    cudaGetSymbolAddress((void**)&xo, g_Xo);

    // Q projection: [4096,1024] @ [1024,1024] + bq  (split-tf32 tensor GEMM)
    gemm_mma_bias_kernel<<<dim3(DM / 128, NTOK / 128), 256>>>(query, Wq, bq, qp, NTOK, DM, DM);
    // K/V projections: [4096,1024] @ [1024,64]  (FFMA)
    gemm_bias_kernel<<<dim3(DKH / 64, NTOK / 64), 256>>>(key, Wk, bk, kp, NTOK, DKH, DM);
    gemm_bias_kernel<<<dim3(DKH / 64, NTOK / 64), 256>>>(value, Wv, bv, vp, NTOK, DKH, DM);
    // Fused masked MQA attention (tf32 tensor cores, m32 warp tile)
    attn_mma_kernel<<<dim3(S_LEN / 128, NH, BATCH), 128>>>(mask);
    // Output projection (split-tf32 tensor GEMM)
    gemm_mma_bias_kernel<<<dim3(DM / 128, NTOK / 128), 256>>>(xo, Wo, bo, out, NTOK, DM, DM);
}

// round 14
// speedup vs baseline: 2.4129x; 1.1252x over previous
#include <cuda_runtime.h>
#include <cstdint>

// Problem constants
#define S_LEN  2048
#define DM     1024
#define NH     16
#define DKH    64
#define BATCH  2
#define NTOK   (BATCH * S_LEN)   // 4096

// Scratch (allocation-free rule: __device__ globals)
__device__ float g_Qp[(size_t)NTOK * DM];    // projected Q  [B*S, D]
__device__ float g_Kp[(size_t)NTOK * DKH];   // projected K  [B*S, d_k]
__device__ float g_Vp[(size_t)NTOK * DKH];   // projected V  [B*S, d_k]
__device__ float g_Xo[(size_t)NTOK * DM];    // attention out [B*S, D]

// ---------------------------------------------------------------------------
// helpers
// ---------------------------------------------------------------------------
__device__ __forceinline__ uint32_t f2tf32(float x) {
    uint32_t r;
    asm("cvt.rna.tf32.f32 %0, %1;" : "=r"(r) : "f"(x));
    return r;
}
__device__ __forceinline__ float tf32r(float x) {
    return __uint_as_float(f2tf32(x));
}

// exp2 on the FMA pipe (no MUFU): round-to-nearest split + deg-5 Taylor on
// [-0.5, 0.5] (rel err ~2.4e-6), exponent via bit-splice.
__device__ __forceinline__ float exp2_fast(float x) {
    x = fmaxf(x, -126.0f);
    int   i = __float2int_rn(x);
    float f = x - (float)i;
    float p = 0.0013333558f;
    p = fmaf(p, f, 0.0096181291f);
    p = fmaf(p, f, 0.0555041087f);
    p = fmaf(p, f, 0.2402265070f);
    p = fmaf(p, f, 0.6931471806f);
    p = fmaf(p, f, 1.0f);
    return p * __int_as_float((i + 127) << 23);
}

__device__ __forceinline__ void mma_tf32(float c[4], const uint32_t a[4],
                                         uint32_t b0, uint32_t b1) {
    asm volatile(
        "mma.sync.aligned.m16n8k8.row.col.f32.tf32.tf32.f32 "
        "{%0,%1,%2,%3}, {%4,%5,%6,%7}, {%8,%9}, {%0,%1,%2,%3};\n"
        : "+f"(c[0]), "+f"(c[1]), "+f"(c[2]), "+f"(c[3])
        : "r"(a[0]), "r"(a[1]), "r"(a[2]), "r"(a[3]), "r"(b0), "r"(b1));
}

// ---------------------------------------------------------------------------
// Small GEMM (K/V projections, N=64): FFMA, register-prefetch pipelined.
// ---------------------------------------------------------------------------
__global__ __launch_bounds__(256) void gemm_bias_kernel(
    const float* __restrict__ A, const float* __restrict__ B,
    const float* __restrict__ bias, float* __restrict__ C,
    int M, int N, int K)
{
    __shared__ float As[16][68];
    __shared__ float Bs[16][68];

    const int tid = threadIdx.x;
    const int tx  = tid & 15;
    const int ty  = tid >> 4;
    const int m0  = blockIdx.y << 6;
    const int n0  = blockIdx.x << 6;

    const int ar = tid >> 2;
    const int ak = (tid & 3) << 2;
    const int br = tid >> 4;
    const int bn = (tid & 15) << 2;

    float acc[4][4];
#pragma unroll
    for (int i = 0; i < 4; i++)
#pragma unroll
        for (int j = 0; j < 4; j++) acc[i][j] = 0.0f;

    // prologue: tile 0
    float4 a = *(const float4*)(A + (size_t)(m0 + ar) * K + ak);
    float4 b = *(const float4*)(B + (size_t)br * N + (n0 + bn));
    As[ak + 0][ar] = a.x; As[ak + 1][ar] = a.y;
    As[ak + 2][ar] = a.z; As[ak + 3][ar] = a.w;
    *(float4*)&Bs[br][bn] = b;
    __syncthreads();

    for (int k0 = 16; k0 <= K; k0 += 16) {
        // prefetch next tile into registers (not consumed until after compute)
        float4 an, bnv;
        if (k0 < K) {
            an  = *(const float4*)(A + (size_t)(m0 + ar) * K + (k0 + ak));
            bnv = *(const float4*)(B + (size_t)(k0 + br) * N + (n0 + bn));
        }

#pragma unroll
        for (int kk = 0; kk < 16; kk++) {
            float4 av = *(const float4*)&As[kk][ty << 2];
            float4 bv = *(const float4*)&Bs[kk][tx << 2];
            acc[0][0] += av.x * bv.x; acc[0][1] += av.x * bv.y;
            acc[0][2] += av.x * bv.z; acc[0][3] += av.x * bv.w;
            acc[1][0] += av.y * bv.x; acc[1][1] += av.y * bv.y;
            acc[1][2] += av.y * bv.z; acc[1][3] += av.y * bv.w;
            acc[2][0] += av.z * bv.x; acc[2][1] += av.z * bv.y;
            acc[2][2] += av.z * bv.z; acc[2][3] += av.z * bv.w;
            acc[3][0] += av.w * bv.x; acc[3][1] += av.w * bv.y;
            acc[3][2] += av.w * bv.z; acc[3][3] += av.w * bv.w;
        }

        if (k0 < K) {
            __syncthreads();   // all reads of current tile done
            As[ak + 0][ar] = an.x; As[ak + 1][ar] = an.y;
            As[ak + 2][ar] = an.z; As[ak + 3][ar] = an.w;
            *(float4*)&Bs[br][bn] = bnv;
            __syncthreads();   // next tile visible
        }
    }

    float4 bb = *(const float4*)(bias + n0 + (tx << 2));
#pragma unroll
    for (int i = 0; i < 4; i++) {
        float4 o;
        o.x = acc[i][0] + bb.x;
        o.y = acc[i][1] + bb.y;
        o.z = acc[i][2] + bb.z;
        o.w = acc[i][3] + bb.w;
        *(float4*)(C + (size_t)(m0 + (ty << 2) + i) * N + n0 + (tx << 2)) = o;
    }
}

// ---------------------------------------------------------------------------
// Split-tf32 (3-mma) GEMM for Q and O projections, register-prefetch
// pipelined. v = hi + lo (tf32 each); C = AhBh + AhBl + AlBh.
// 256 thr / 8 warps; block tile 128x128, BK=16; warp tile m32 x n64.
// ---------------------------------------------------------------------------
#define GPAD 136

__global__ __launch_bounds__(256, 2) void gemm_mma_bias_kernel(
    const float* __restrict__ A, const float* __restrict__ B,
    const float* __restrict__ bias, float* __restrict__ C,
    int M, int N, int K)
{
    __shared__ float Ah[16][GPAD], Al[16][GPAD];
    __shared__ float Bh[16][GPAD], Bl[16][GPAD];

    const int tid  = threadIdx.x;
    const int lane = tid & 31;
    const int warp = tid >> 5;
    const int g    = lane >> 2;
    const int t4   = lane & 3;
    const int wm   = warp >> 1;
    const int wn   = warp & 1;
    const int m0   = blockIdx.y << 7;
    const int n0   = blockIdx.x << 7;

    const int ar = tid >> 1;
    const int ak = (tid & 1) << 3;
    const int br = tid >> 4;
    const int bn = (tid & 15) << 3;

    float acc[2][8][4];
#pragma unroll
    for (int f = 0; f < 2; f++)
#pragma unroll
        for (int j = 0; j < 8; j++)
#pragma unroll
            for (int r = 0; r < 4; r++) acc[f][j][r] = 0.0f;

    // split+store helper values live in av/bv registers
    float av[8], bv[8];
    *(float4*)&av[0] = *(const float4*)(A + (size_t)(m0 + ar) * K + ak);
    *(float4*)&av[4] = *(const float4*)(A + (size_t)(m0 + ar) * K + (ak + 4));
    *(float4*)&bv[0] = *(const float4*)(B + (size_t)br * N + (n0 + bn));
    *(float4*)&bv[4] = *(const float4*)(B + (size_t)br * N + (n0 + bn + 4));
    {
#pragma unroll
        for (int i = 0; i < 8; i++) {
            float hi = tf32r(av[i]);
            Ah[ak + i][ar] = hi;
            Al[ak + i][ar] = tf32r(av[i] - hi);
        }
        float bh[8], bl[8];
#pragma unroll
        for (int i = 0; i < 8; i++) {
            bh[i] = tf32r(bv[i]);
            bl[i] = tf32r(bv[i] - bh[i]);
        }
        *(float4*)&Bh[br][bn]     = *(float4*)&bh[0];
        *(float4*)&Bh[br][bn + 4] = *(float4*)&bh[4];
        *(float4*)&Bl[br][bn]     = *(float4*)&bl[0];
        *(float4*)&Bl[br][bn + 4] = *(float4*)&bl[4];
    }
    __syncthreads();

    for (int k0 = 16; k0 <= K; k0 += 16) {
        // prefetch next tile (consumed after compute)
        if (k0 < K) {
            *(float4*)&av[0] = *(const float4*)(A + (size_t)(m0 + ar) * K + (k0 + ak));
            *(float4*)&av[4] = *(const float4*)(A + (size_t)(m0 + ar) * K + (k0 + ak + 4));
            *(float4*)&bv[0] = *(const float4*)(B + (size_t)(k0 + br) * N + (n0 + bn));
            *(float4*)&bv[4] = *(const float4*)(B + (size_t)(k0 + br) * N + (n0 + bn + 4));
        }

        // compute on resident tile
#pragma unroll
        for (int ks = 0; ks < 16; ks += 8) {
            uint32_t ah[2][4], al[2][4];
#pragma unroll
            for (int f = 0; f < 2; f++) {
                const int m = wm * 32 + f * 16;
                ah[f][0] = __float_as_uint(Ah[ks + t4][m + g]);
                ah[f][1] = __float_as_uint(Ah[ks + t4][m + g + 8]);
                ah[f][2] = __float_as_uint(Ah[ks + t4 + 4][m + g]);
                ah[f][3] = __float_as_uint(Ah[ks + t4 + 4][m + g + 8]);
                al[f][0] = __float_as_uint(Al[ks + t4][m + g]);
                al[f][1] = __float_as_uint(Al[ks + t4][m + g + 8]);
                al[f][2] = __float_as_uint(Al[ks + t4 + 4][m + g]);
                al[f][3] = __float_as_uint(Al[ks + t4 + 4][m + g + 8]);
            }
#pragma unroll
            for (int j = 0; j < 8; j++) {
                const int n = wn * 64 + j * 8 + g;
                uint32_t bh0 = __float_as_uint(Bh[ks + t4][n]);
                uint32_t bh1 = __float_as_uint(Bh[ks + t4 + 4][n]);
                uint32_t bl0 = __float_as_uint(Bl[ks + t4][n]);
                uint32_t bl1 = __float_as_uint(Bl[ks + t4 + 4][n]);
#pragma unroll
                for (int f = 0; f < 2; f++) {
                    mma_tf32(acc[f][j], ah[f], bh0, bh1);
                    mma_tf32(acc[f][j], ah[f], bl0, bl1);
                    mma_tf32(acc[f][j], al[f], bh0, bh1);
                }
            }
        }

        if (k0 < K) {
            __syncthreads();   // reads of current tile complete
#pragma unroll
            for (int i = 0; i < 8; i++) {
                float hi = tf32r(av[i]);
                Ah[ak + i][ar] = hi;
                Al[ak + i][ar] = tf32r(av[i] - hi);
            }
            float bh[8], bl[8];
#pragma unroll
            for (int i = 0; i < 8; i++) {
                bh[i] = tf32r(bv[i]);
                bl[i] = tf32r(bv[i] - bh[i]);
            }
            *(float4*)&Bh[br][bn]     = *(float4*)&bh[0];
            *(float4*)&Bh[br][bn + 4] = *(float4*)&bh[4];
            *(float4*)&Bl[br][bn]     = *(float4*)&bl[0];
            *(float4*)&Bl[br][bn + 4] = *(float4*)&bl[4];
            __syncthreads();   // next tile visible
        }
    }

    // epilogue: bias + store
#pragma unroll
    for (int j = 0; j < 8; j++) {
        const int n = n0 + wn * 64 + j * 8 + t4 * 2;
        float2 bs = *(const float2*)(bias + n);
#pragma unroll
        for (int f = 0; f < 2; f++) {
            const int r = m0 + wm * 32 + f * 16 + g;
            float2 o0, o1;
            o0.x = acc[f][j][0] + bs.x; o0.y = acc[f][j][1] + bs.y;
            o1.x = acc[f][j][2] + bs.x; o1.y = acc[f][j][3] + bs.y;
            *(float2*)(C + (size_t)r * N + n)       = o0;
            *(float2*)(C + (size_t)(r + 8) * N + n) = o1;
        }
    }
}

// ---------------------------------------------------------------------------
// Fused masked MQA attention — tf32 mma.sync, warp tile m32 (f=0,1), KT=32.
// UNCHANGED from R13 (386.6 us measured).
// ---------------------------------------------------------------------------
#define KT2   32
#define KVPAD 68   // == 4 (mod 32)
#define VPAD  72   // == 8 (mod 32)

__global__ __launch_bounds__(128, 2) void attn_mma_kernel(const int* __restrict__ mask)
{
    __shared__ float Kv[KT2][KVPAD];   // Kv[kseq][d]
    __shared__ float Vs[KT2][VPAD];    // Vs[kseq][d]

    const int tid  = threadIdx.x;
    const int lane = tid & 31;
    const int warp = tid >> 5;
    const int g    = lane >> 2;
    const int t4   = lane & 3;
    const int q0   = blockIdx.x << 7;       // 128 q-rows per block
    const int h    = blockIdx.y;
    const int b    = blockIdx.z;

    const float* Qb = g_Qp + (size_t)b * S_LEN * DM + h * DKH;
    const float* Kb = g_Kp + (size_t)b * S_LEN * DKH;
    const float* Vb = g_Vp + (size_t)b * S_LEN * DKH;
    const int*   Mb = mask + (size_t)b * S_LEN * S_LEN;

    const int rbase = q0 + warp * 32;
    const float qsc = 0.125f * 1.4426950408889634f;   // fold 1/8 and log2(e)

    uint32_t qa[2][8][4];
#pragma unroll
    for (int f = 0; f < 2; f++) {
        const int rA = rbase + f * 16 + g;
        const int rB = rA + 8;
#pragma unroll
        for (int s = 0; s < 8; s++) {
            qa[f][s][0] = f2tf32(Qb[(size_t)rA * DM + s * 8 + t4]     * qsc);
            qa[f][s][1] = f2tf32(Qb[(size_t)rB * DM + s * 8 + t4]     * qsc);
            qa[f][s][2] = f2tf32(Qb[(size_t)rA * DM + s * 8 + t4 + 4] * qsc);
            qa[f][s][3] = f2tf32(Qb[(size_t)rB * DM + s * 8 + t4 + 4] * qsc);
        }
    }

    float m_[2][2], l_[2][2];
#pragma unroll
    for (int f = 0; f < 2; f++) {
        m_[f][0] = -1e30f; m_[f][1] = -1e30f;
        l_[f][0] = 0.0f;   l_[f][1] = 0.0f;
    }
    float of[2][8][4];
#pragma unroll
    for (int f = 0; f < 2; f++)
#pragma unroll
        for (int nb = 0; nb < 8; nb++)
#pragma unroll
            for (int r = 0; r < 4; r++) of[f][nb][r] = 0.0f;

    for (int k0 = 0; k0 < S_LEN; k0 += KT2) {
        __syncthreads();
        {
            const int r  = tid >> 2;
            const int cq = tid & 3;
#pragma unroll
            for (int it = 0; it < 4; it++) {
                const int c = (cq + it * 4) << 2;
                float4 kv = *(const float4*)(Kb + (size_t)(k0 + r) * DKH + c);
                kv.x = tf32r(kv.x); kv.y = tf32r(kv.y);
                kv.z = tf32r(kv.z); kv.w = tf32r(kv.w);
                *(float4*)&Kv[r][c] = kv;
                float4 vv = *(const float4*)(Vb + (size_t)(k0 + r) * DKH + c);
                vv.x = tf32r(vv.x); vv.y = tf32r(vv.y);
                vv.z = tf32r(vv.z); vv.w = tf32r(vv.w);
                *(float4*)&Vs[r][c] = vv;
            }
        }
        __syncthreads();

        float sc[2][4][4];
#pragma unroll
        for (int j = 0; j < 4; j++) {
#pragma unroll
            for (int f = 0; f < 2; f++)
                sc[f][j][0] = sc[f][j][1] = sc[f][j][2] = sc[f][j][3] = 0.0f;
#pragma unroll
            for (int s = 0; s < 8; s++) {
                uint32_t b0 = __float_as_uint(Kv[j * 8 + g][s * 8 + t4]);
                uint32_t b1 = __float_as_uint(Kv[j * 8 + g][s * 8 + t4 + 4]);
                mma_tf32(sc[0][j], qa[0][s], b0, b1);
                mma_tf32(sc[1][j], qa[1][s], b0, b1);
            }
        }

#pragma unroll
        for (int f = 0; f < 2; f++) {
            const int rA = rbase + f * 16 + g;
            const int rB = rA + 8;
#pragma unroll
            for (int j = 0; j < 4; j++) {
                const int c0 = k0 + j * 8 + t4 * 2;
                int2 mA = *(const int2*)(Mb + (size_t)rA * S_LEN + c0);
                int2 mB = *(const int2*)(Mb + (size_t)rB * S_LEN + c0);
                sc[f][j][0] = mA.x ? sc[f][j][0] : -1.0e9f;
                sc[f][j][1] = mA.y ? sc[f][j][1] : -1.0e9f;
                sc[f][j][2] = mB.x ? sc[f][j][2] : -1.0e9f;
                sc[f][j][3] = mB.y ? sc[f][j][3] : -1.0e9f;
            }

            float mx0 = -1e30f, mx1 = -1e30f;
#pragma unroll
            for (int j = 0; j < 4; j++) {
                mx0 = fmaxf(mx0, fmaxf(sc[f][j][0], sc[f][j][1]));
                mx1 = fmaxf(mx1, fmaxf(sc[f][j][2], sc[f][j][3]));
            }
            mx0 = fmaxf(mx0, __shfl_xor_sync(0xffffffffu, mx0, 1));
            mx0 = fmaxf(mx0, __shfl_xor_sync(0xffffffffu, mx0, 2));
            mx1 = fmaxf(mx1, __shfl_xor_sync(0xffffffffu, mx1, 1));
            mx1 = fmaxf(mx1, __shfl_xor_sync(0xffffffffu, mx1, 2));

            const float mn0 = fmaxf(m_[f][0], mx0);
            const float mn1 = fmaxf(m_[f][1], mx1);
            const float corr0 = exp2_fast(m_[f][0] - mn0);
            const float corr1 = exp2_fast(m_[f][1] - mn1);
            m_[f][0] = mn0; m_[f][1] = mn1;

            float rs0 = 0.0f, rs1 = 0.0f;
#pragma unroll
            for (int j = 0; j < 4; j++) {
                sc[f][j][0] = exp2_fast(sc[f][j][0] - mn0);
                sc[f][j][1] = exp2_fast(sc[f][j][1] - mn0);
                sc[f][j][2] = exp2_fast(sc[f][j][2] - mn1);
                sc[f][j][3] = exp2_fast(sc[f][j][3] - mn1);
                rs0 += sc[f][j][0] + sc[f][j][1];
                rs1 += sc[f][j][2] + sc[f][j][3];
            }
            rs0 += __shfl_xor_sync(0xffffffffu, rs0, 1);
            rs0 += __shfl_xor_sync(0xffffffffu, rs0, 2);
            rs1 += __shfl_xor_sync(0xffffffffu, rs1, 1);
            rs1 += __shfl_xor_sync(0xffffffffu, rs1, 2);
            l_[f][0] = l_[f][0] * corr0 + rs0;
            l_[f][1] = l_[f][1] * corr1 + rs1;

#pragma unroll
            for (int nb = 0; nb < 8; nb++) {
                of[f][nb][0] *= corr0; of[f][nb][1] *= corr0;
                of[f][nb][2] *= corr1; of[f][nb][3] *= corr1;
            }
        }

        const int base = lane & ~3;
        const int src0 = base | (t4 >> 1);
        const int src2 = src0 + 2;
        const bool odd = (t4 & 1) != 0;
#pragma unroll
        for (int s = 0; s < 4; s++) {
            uint32_t pa[2][4];
#pragma unroll
            for (int f = 0; f < 2; f++) {
                float v00 = __shfl_sync(0xffffffffu, sc[f][s][0], src0);
                float v01 = __shfl_sync(0xffffffffu, sc[f][s][1], src0);
                float w00 = __shfl_sync(0xffffffffu, sc[f][s][2], src0);
                float w01 = __shfl_sync(0xffffffffu, sc[f][s][3], src0);
                float v20 = __shfl_sync(0xffffffffu, sc[f][s][0], src2);
                float v21 = __shfl_sync(0xffffffffu, sc[f][s][1], src2);
                float w20 = __shfl_sync(0xffffffffu, sc[f][s][2], src2);
                float w21 = __shfl_sync(0xffffffffu, sc[f][s][3], src2);
                pa[f][0] = f2tf32(odd ? v01 : v00);
                pa[f][1] = f2tf32(odd ? w01 : w00);
                pa[f][2] = f2tf32(odd ? v21 : v20);
                pa[f][3] = f2tf32(odd ? w21 : w20);
            }
#pragma unroll
            for (int nb = 0; nb < 8; nb++) {
                uint32_t b0 = __float_as_uint(Vs[s * 8 + t4][nb * 8 + g]);
                uint32_t b1 = __float_as_uint(Vs[s * 8 + t4 + 4][nb * 8 + g]);
                mma_tf32(of[0][nb], pa[0], b0, b1);
                mma_tf32(of[1][nb], pa[1], b0, b1);
            }
        }
    }

    // Epilogue: normalize, write g_Xo[b, q, h*64 + d]
#pragma unroll
    for (int f = 0; f < 2; f++) {
        const int rA = rbase + f * 16 + g;
        const int rB = rA + 8;
        const float il0 = 1.0f / l_[f][0];
        const float il1 = 1.0f / l_[f][1];
#pragma unroll
        for (int nb = 0; nb < 8; nb++) {
            float2 o0, o1;
            o0.x = of[f][nb][0] * il0; o0.y = of[f][nb][1] * il0;
            o1.x = of[f][nb][2] * il1; o1.y = of[f][nb][3] * il1;
            const int col = h * DKH + nb * 8 + t4 * 2;
            *(float2*)(g_Xo + (size_t)(b * S_LEN + rA) * DM + col) = o0;
            *(float2*)(g_Xo + (size_t)(b * S_LEN + rB) * DM + col) = o1;
        }
    }
}

// ---------------------------------------------------------------------------
extern "C" void kernel_launch(void* const* d_in, const int* in_sizes, int n_in,
                              void* d_out, int out_size)
{
    const float* query = (const float*)d_in[0];
    const float* key   = (const float*)d_in[1];
    const float* value = (const float*)d_in[2];
    const int*   mask  = (const int*)  d_in[3];
    const float* Wq    = (const float*)d_in[4];
    const float* bq    = (const float*)d_in[5];
    const float* Wk    = (const float*)d_in[6];
    const float* bk    = (const float*)d_in[7];
    const float* Wv    = (const float*)d_in[8];
    const float* bv    = (const float*)d_in[9];
    const float* Wo    = (const float*)d_in[10];
    const float* bo    = (const float*)d_in[11];
    float* out = (float*)d_out;

    float *qp, *kp, *vp, *xo;
    cudaGetSymbolAddress((void**)&qp, g_Qp);
    cudaGetSymbolAddress((void**)&kp, g_Kp);
    cudaGetSymbolAddress((void**)&vp, g_Vp);
    cudaGetSymbolAddress((void**)&xo, g_Xo);

    // Q projection: [4096,1024] @ [1024,1024] + bq  (split-tf32, pipelined)
    gemm_mma_bias_kernel<<<dim3(DM / 128, NTOK / 128), 256>>>(query, Wq, bq, qp, NTOK, DM, DM);
    // K/V projections: [4096,1024] @ [1024,64]  (FFMA, pipelined)
    gemm_bias_kernel<<<dim3(DKH / 64, NTOK / 64), 256>>>(key, Wk, bk, kp, NTOK, DKH, DM);
    gemm_bias_kernel<<<dim3(DKH / 64, NTOK / 64), 256>>>(value, Wv, bv, vp, NTOK, DKH, DM);
    // Fused masked MQA attention (tf32 tensor cores, m32 warp tile)
    attn_mma_kernel<<<dim3(S_LEN / 128, NH, BATCH), 128>>>(mask);
    // Output projection (split-tf32, pipelined)
    gemm_mma_bias_kernel<<<dim3(DM / 128, NTOK / 128), 256>>>(xo, Wo, bo, out, NTOK, DM, DM);
}

// round 15
// speedup vs baseline: 2.5925x; 1.0744x over previous
#include <cuda_runtime.h>
#include <cstdint>

// Problem constants
#define S_LEN  2048
#define DM     1024
#define NH     16
#define DKH    64
#define BATCH  2
#define NTOK   (BATCH * S_LEN)   // 4096

// Scratch (allocation-free rule: __device__ globals)
__device__ float g_Qp[(size_t)NTOK * DM];    // projected Q  [B*S, D]
__device__ float g_Kp[(size_t)NTOK * DKH];   // projected K  [B*S, d_k]
__device__ float g_Vp[(size_t)NTOK * DKH];   // projected V  [B*S, d_k]
__device__ float g_Xo[(size_t)NTOK * DM];    // attention out [B*S, D]

// ---------------------------------------------------------------------------
// helpers
// ---------------------------------------------------------------------------
__device__ __forceinline__ uint32_t f2tf32(float x) {
    uint32_t r;
    asm("cvt.rna.tf32.f32 %0, %1;" : "=r"(r) : "f"(x));
    return r;
}
__device__ __forceinline__ float tf32r(float x) {
    return __uint_as_float(f2tf32(x));
}

// exp2 on the FMA pipe (no MUFU): round-to-nearest split + deg-5 Taylor on
// [-0.5, 0.5] (rel err ~2.4e-6), exponent via bit-splice.
__device__ __forceinline__ float exp2_fast(float x) {
    x = fmaxf(x, -126.0f);
    int   i = __float2int_rn(x);
    float f = x - (float)i;
    float p = 0.0013333558f;
    p = fmaf(p, f, 0.0096181291f);
    p = fmaf(p, f, 0.0555041087f);
    p = fmaf(p, f, 0.2402265070f);
    p = fmaf(p, f, 0.6931471806f);
    p = fmaf(p, f, 1.0f);
    return p * __int_as_float((i + 127) << 23);
}

__device__ __forceinline__ void mma_tf32(float c[4], const uint32_t a[4],
                                         uint32_t b0, uint32_t b1) {
    asm volatile(
        "mma.sync.aligned.m16n8k8.row.col.f32.tf32.tf32.f32 "
        "{%0,%1,%2,%3}, {%4,%5,%6,%7}, {%8,%9}, {%0,%1,%2,%3};\n"
        : "+f"(c[0]), "+f"(c[1]), "+f"(c[2]), "+f"(c[3])
        : "r"(a[0]), "r"(a[1]), "r"(a[2]), "r"(a[3]), "r"(b0), "r"(b1));
}

// ---------------------------------------------------------------------------
// Merged K+V projections: one launch, blockIdx.z selects (key,Wk,bk->Kp) or
// (value,Wv,bv->Vp). FFMA 64x64 tile, register-prefetch pipelined.
// ---------------------------------------------------------------------------
__global__ __launch_bounds__(256) void kv_gemm_kernel(
    const float* __restrict__ Kin, const float* __restrict__ Wk,
    const float* __restrict__ bk,
    const float* __restrict__ Vin, const float* __restrict__ Wv,
    const float* __restrict__ bv)
{
    const int z = blockIdx.z;
    const float* A    = z ? Vin : Kin;
    const float* B    = z ? Wv  : Wk;
    const float* bias = z ? bv  : bk;
    float* C;
    {
        // __device__ symbols are directly addressable in device code
        C = z ? g_Vp : g_Kp;
    }
    const int M = NTOK, N = DKH, K = DM;

    __shared__ float As[16][68];
    __shared__ float Bs[16][68];

    const int tid = threadIdx.x;
    const int tx  = tid & 15;
    const int ty  = tid >> 4;
    const int m0  = blockIdx.y << 6;
    const int n0  = 0;   // N == 64, single n-tile

    const int ar = tid >> 2;
    const int ak = (tid & 3) << 2;
    const int br = tid >> 4;
    const int bn = (tid & 15) << 2;

    float acc[4][4];
#pragma unroll
    for (int i = 0; i < 4; i++)
#pragma unroll
        for (int j = 0; j < 4; j++) acc[i][j] = 0.0f;

    // prologue: tile 0
    float4 a = *(const float4*)(A + (size_t)(m0 + ar) * K + ak);
    float4 b = *(const float4*)(B + (size_t)br * N + (n0 + bn));
    As[ak + 0][ar] = a.x; As[ak + 1][ar] = a.y;
    As[ak + 2][ar] = a.z; As[ak + 3][ar] = a.w;
    *(float4*)&Bs[br][bn] = b;
    __syncthreads();

    for (int k0 = 16; k0 <= K; k0 += 16) {
        float4 an, bnv;
        if (k0 < K) {
            an  = *(const float4*)(A + (size_t)(m0 + ar) * K + (k0 + ak));
            bnv = *(const float4*)(B + (size_t)(k0 + br) * N + (n0 + bn));
        }

#pragma unroll
        for (int kk = 0; kk < 16; kk++) {
            float4 av = *(const float4*)&As[kk][ty << 2];
            float4 bv4 = *(const float4*)&Bs[kk][tx << 2];
            acc[0][0] += av.x * bv4.x; acc[0][1] += av.x * bv4.y;
            acc[0][2] += av.x * bv4.z; acc[0][3] += av.x * bv4.w;
            acc[1][0] += av.y * bv4.x; acc[1][1] += av.y * bv4.y;
            acc[1][2] += av.y * bv4.z; acc[1][3] += av.y * bv4.w;
            acc[2][0] += av.z * bv4.x; acc[2][1] += av.z * bv4.y;
            acc[2][2] += av.z * bv4.z; acc[2][3] += av.z * bv4.w;
            acc[3][0] += av.w * bv4.x; acc[3][1] += av.w * bv4.y;
            acc[3][2] += av.w * bv4.z; acc[3][3] += av.w * bv4.w;
        }

        if (k0 < K) {
            __syncthreads();
            As[ak + 0][ar] = an.x; As[ak + 1][ar] = an.y;
            As[ak + 2][ar] = an.z; As[ak + 3][ar] = an.w;
            *(float4*)&Bs[br][bn] = bnv;
            __syncthreads();
        }
    }

    float4 bb = *(const float4*)(bias + n0 + (tx << 2));
#pragma unroll
    for (int i = 0; i < 4; i++) {
        float4 o;
        o.x = acc[i][0] + bb.x;
        o.y = acc[i][1] + bb.y;
        o.z = acc[i][2] + bb.z;
        o.w = acc[i][3] + bb.w;
        *(float4*)(C + (size_t)(m0 + (ty << 2) + i) * N + n0 + (tx << 2)) = o;
    }
}

// ---------------------------------------------------------------------------
// Split-tf32 (3-mma) GEMM for Q and O projections, register-prefetch
// pipelined (unchanged from R14).
// ---------------------------------------------------------------------------
#define GPAD 136

__global__ __launch_bounds__(256, 2) void gemm_mma_bias_kernel(
    const float* __restrict__ A, const float* __restrict__ B,
    const float* __restrict__ bias, float* __restrict__ C,
    int M, int N, int K)
{
    __shared__ float Ah[16][GPAD], Al[16][GPAD];
    __shared__ float Bh[16][GPAD], Bl[16][GPAD];

    const int tid  = threadIdx.x;
    const int lane = tid & 31;
    const int warp = tid >> 5;
    const int g    = lane >> 2;
    const int t4   = lane & 3;
    const int wm   = warp >> 1;
    const int wn   = warp & 1;
    const int m0   = blockIdx.y << 7;
    const int n0   = blockIdx.x << 7;

    const int ar = tid >> 1;
    const int ak = (tid & 1) << 3;
    const int br = tid >> 4;
    const int bn = (tid & 15) << 3;

    float acc[2][8][4];
#pragma unroll
    for (int f = 0; f < 2; f++)
#pragma unroll
        for (int j = 0; j < 8; j++)
#pragma unroll
            for (int r = 0; r < 4; r++) acc[f][j][r] = 0.0f;

    float av[8], bv[8];
    *(float4*)&av[0] = *(const float4*)(A + (size_t)(m0 + ar) * K + ak);
    *(float4*)&av[4] = *(const float4*)(A + (size_t)(m0 + ar) * K + (ak + 4));
    *(float4*)&bv[0] = *(const float4*)(B + (size_t)br * N + (n0 + bn));
    *(float4*)&bv[4] = *(const float4*)(B + (size_t)br * N + (n0 + bn + 4));
    {
#pragma unroll
        for (int i = 0; i < 8; i++) {
            float hi = tf32r(av[i]);
            Ah[ak + i][ar] = hi;
            Al[ak + i][ar] = tf32r(av[i] - hi);
        }
        float bh[8], bl[8];
#pragma unroll
        for (int i = 0; i < 8; i++) {
            bh[i] = tf32r(bv[i]);
            bl[i] = tf32r(bv[i] - bh[i]);
        }
        *(float4*)&Bh[br][bn]     = *(float4*)&bh[0];
        *(float4*)&Bh[br][bn + 4] = *(float4*)&bh[4];
        *(float4*)&Bl[br][bn]     = *(float4*)&bl[0];
        *(float4*)&Bl[br][bn + 4] = *(float4*)&bl[4];
    }
    __syncthreads();

    for (int k0 = 16; k0 <= K; k0 += 16) {
        if (k0 < K) {
            *(float4*)&av[0] = *(const float4*)(A + (size_t)(m0 + ar) * K + (k0 + ak));
            *(float4*)&av[4] = *(const float4*)(A + (size_t)(m0 + ar) * K + (k0 + ak + 4));
            *(float4*)&bv[0] = *(const float4*)(B + (size_t)(k0 + br) * N + (n0 + bn));
            *(float4*)&bv[4] = *(const float4*)(B + (size_t)(k0 + br) * N + (n0 + bn + 4));
        }

#pragma unroll
        for (int ks = 0; ks < 16; ks += 8) {
            uint32_t ah[2][4], al[2][4];
#pragma unroll
            for (int f = 0; f < 2; f++) {
                const int m = wm * 32 + f * 16;
                ah[f][0] = __float_as_uint(Ah[ks + t4][m + g]);
                ah[f][1] = __float_as_uint(Ah[ks + t4][m + g + 8]);
                ah[f][2] = __float_as_uint(Ah[ks + t4 + 4][m + g]);
                ah[f][3] = __float_as_uint(Ah[ks + t4 + 4][m + g + 8]);
                al[f][0] = __float_as_uint(Al[ks + t4][m + g]);
                al[f][1] = __float_as_uint(Al[ks + t4][m + g + 8]);
                al[f][2] = __float_as_uint(Al[ks + t4 + 4][m + g]);
                al[f][3] = __float_as_uint(Al[ks + t4 + 4][m + g + 8]);
            }
#pragma unroll
            for (int j = 0; j < 8; j++) {
                const int n = wn * 64 + j * 8 + g;
                uint32_t bh0 = __float_as_uint(Bh[ks + t4][n]);
                uint32_t bh1 = __float_as_uint(Bh[ks + t4 + 4][n]);
                uint32_t bl0 = __float_as_uint(Bl[ks + t4][n]);
                uint32_t bl1 = __float_as_uint(Bl[ks + t4 + 4][n]);
#pragma unroll
                for (int f = 0; f < 2; f++) {
                    mma_tf32(acc[f][j], ah[f], bh0, bh1);
                    mma_tf32(acc[f][j], ah[f], bl0, bl1);
                    mma_tf32(acc[f][j], al[f], bh0, bh1);
                }
            }
        }

        if (k0 < K) {
            __syncthreads();
#pragma unroll
            for (int i = 0; i < 8; i++) {
                float hi = tf32r(av[i]);
                Ah[ak + i][ar] = hi;
                Al[ak + i][ar] = tf32r(av[i] - hi);
            }
            float bh[8], bl[8];
#pragma unroll
            for (int i = 0; i < 8; i++) {
                bh[i] = tf32r(bv[i]);
                bl[i] = tf32r(bv[i] - bh[i]);
            }
            *(float4*)&Bh[br][bn]     = *(float4*)&bh[0];
            *(float4*)&Bh[br][bn + 4] = *(float4*)&bh[4];
            *(float4*)&Bl[br][bn]     = *(float4*)&bl[0];
            *(float4*)&Bl[br][bn + 4] = *(float4*)&bl[4];
            __syncthreads();
        }
    }

#pragma unroll
    for (int j = 0; j < 8; j++) {
        const int n = n0 + wn * 64 + j * 8 + t4 * 2;
        float2 bs = *(const float2*)(bias + n);
#pragma unroll
        for (int f = 0; f < 2; f++) {
            const int r = m0 + wm * 32 + f * 16 + g;
            float2 o0, o1;
            o0.x = acc[f][j][0] + bs.x; o0.y = acc[f][j][1] + bs.y;
            o1.x = acc[f][j][2] + bs.x; o1.y = acc[f][j][3] + bs.y;
            *(float2*)(C + (size_t)r * N + n)       = o0;
            *(float2*)(C + (size_t)(r + 8) * N + n) = o1;
        }
    }
}

// ---------------------------------------------------------------------------
// Fused masked MQA attention — tf32 mma.sync, warp tile m32 (f=0,1), KT=32.
// SHUFFLE-FREE PV: V rows are consumed through the k-permutation
// pi = {0,2,4,6,1,3,5,7}, which makes the score C-frag a valid P A-frag by
// pure register renaming (pa = {c0, c2, c1, c3}). B-frag rows become
// {s*8+2*t4, s*8+2*t4+1}; with VPAD=68 the bank is (8*t4+8*nb+g) mod 32 ->
// conflict-free. Identical product set => identical numerics.
// ---------------------------------------------------------------------------
#define KT2   32
#define KVPAD 68   // == 4 (mod 32)
#define VPAD  68   // == 4 (mod 32); conflict-free for permuted row pairs

__global__ __launch_bounds__(128, 2) void attn_mma_kernel(const int* __restrict__ mask)
{
    __shared__ float Kv[KT2][KVPAD];   // Kv[kseq][d]
    __shared__ float Vs[KT2][VPAD];    // Vs[kseq][d]

    const int tid  = threadIdx.x;
    const int lane = tid & 31;
    const int warp = tid >> 5;
    const int g    = lane >> 2;
    const int t4   = lane & 3;
    const int q0   = blockIdx.x << 7;       // 128 q-rows per block
    const int h    = blockIdx.y;
    const int b    = blockIdx.z;

    const float* Qb = g_Qp + (size_t)b * S_LEN * DM + h * DKH;
    const float* Kb = g_Kp + (size_t)b * S_LEN * DKH;
    const float* Vb = g_Vp + (size_t)b * S_LEN * DKH;
    const int*   Mb = mask + (size_t)b * S_LEN * S_LEN;

    const int rbase = q0 + warp * 32;
    const float qsc = 0.125f * 1.4426950408889634f;   // fold 1/8 and log2(e)

    uint32_t qa[2][8][4];
#pragma unroll
    for (int f = 0; f < 2; f++) {
        const int rA = rbase + f * 16 + g;
        const int rB = rA + 8;
#pragma unroll
        for (int s = 0; s < 8; s++) {
            qa[f][s][0] = f2tf32(Qb[(size_t)rA * DM + s * 8 + t4]     * qsc);
            qa[f][s][1] = f2tf32(Qb[(size_t)rB * DM + s * 8 + t4]     * qsc);
            qa[f][s][2] = f2tf32(Qb[(size_t)rA * DM + s * 8 + t4 + 4] * qsc);
            qa[f][s][3] = f2tf32(Qb[(size_t)rB * DM + s * 8 + t4 + 4] * qsc);
        }
    }

    float m_[2][2], l_[2][2];
#pragma unroll
    for (int f = 0; f < 2; f++) {
        m_[f][0] = -1e30f; m_[f][1] = -1e30f;
        l_[f][0] = 0.0f;   l_[f][1] = 0.0f;
    }
    float of[2][8][4];
#pragma unroll
    for (int f = 0; f < 2; f++)
#pragma unroll
        for (int nb = 0; nb < 8; nb++)
#pragma unroll
            for (int r = 0; r < 4; r++) of[f][nb][r] = 0.0f;

    for (int k0 = 0; k0 < S_LEN; k0 += KT2) {
        __syncthreads();
        // Load K and V tiles, natural layout, tf32-rounded, float4 STS.
        {
            const int r  = tid >> 2;          // 0..31 (kseq row)
            const int cq = tid & 3;           // col-quad base
#pragma unroll
            for (int it = 0; it < 4; it++) {
                const int c = (cq + it * 4) << 2;   // 0..60
                float4 kv = *(const float4*)(Kb + (size_t)(k0 + r) * DKH + c);
                kv.x = tf32r(kv.x); kv.y = tf32r(kv.y);
                kv.z = tf32r(kv.z); kv.w = tf32r(kv.w);
                *(float4*)&Kv[r][c] = kv;
                float4 vv = *(const float4*)(Vb + (size_t)(k0 + r) * DKH + c);
                vv.x = tf32r(vv.x); vv.y = tf32r(vv.y);
                vv.z = tf32r(vv.z); vv.w = tf32r(vv.w);
                *(float4*)&Vs[r][c] = vv;
            }
        }
        __syncthreads();

        // Scores: sc[f][j] = m16x8 C-frag, cols k0+j*8..+7, j in 0..3
        float sc[2][4][4];
#pragma unroll
        for (int j = 0; j < 4; j++) {
#pragma unroll
            for (int f = 0; f < 2; f++)
                sc[f][j][0] = sc[f][j][1] = sc[f][j][2] = sc[f][j][3] = 0.0f;
#pragma unroll
            for (int s = 0; s < 8; s++) {
                uint32_t b0 = __float_as_uint(Kv[j * 8 + g][s * 8 + t4]);
                uint32_t b1 = __float_as_uint(Kv[j * 8 + g][s * 8 + t4 + 4]);
                mma_tf32(sc[0][j], qa[0][s], b0, b1);
                mma_tf32(sc[1][j], qa[1][s], b0, b1);
            }
        }

        // Mask + online softmax per f (base-2 domain).
#pragma unroll
        for (int f = 0; f < 2; f++) {
            const int rA = rbase + f * 16 + g;
            const int rB = rA + 8;
#pragma unroll
            for (int j = 0; j < 4; j++) {
                const int c0 = k0 + j * 8 + t4 * 2;
                int2 mA = *(const int2*)(Mb + (size_t)rA * S_LEN + c0);
                int2 mB = *(const int2*)(Mb + (size_t)rB * S_LEN + c0);
                sc[f][j][0] = mA.x ? sc[f][j][0] : -1.0e9f;
                sc[f][j][1] = mA.y ? sc[f][j][1] : -1.0e9f;
                sc[f][j][2] = mB.x ? sc[f][j][2] : -1.0e9f;
                sc[f][j][3] = mB.y ? sc[f][j][3] : -1.0e9f;
            }

            float mx0 = -1e30f, mx1 = -1e30f;
#pragma unroll
            for (int j = 0; j < 4; j++) {
                mx0 = fmaxf(mx0, fmaxf(sc[f][j][0], sc[f][j][1]));
                mx1 = fmaxf(mx1, fmaxf(sc[f][j][2], sc[f][j][3]));
            }
            mx0 = fmaxf(mx0, __shfl_xor_sync(0xffffffffu, mx0, 1));
            mx0 = fmaxf(mx0, __shfl_xor_sync(0xffffffffu, mx0, 2));
            mx1 = fmaxf(mx1, __shfl_xor_sync(0xffffffffu, mx1, 1));
            mx1 = fmaxf(mx1, __shfl_xor_sync(0xffffffffu, mx1, 2));

            const float mn0 = fmaxf(m_[f][0], mx0);
            const float mn1 = fmaxf(m_[f][1], mx1);
            const float corr0 = exp2_fast(m_[f][0] - mn0);
            const float corr1 = exp2_fast(m_[f][1] - mn1);
            m_[f][0] = mn0; m_[f][1] = mn1;

            float rs0 = 0.0f, rs1 = 0.0f;
#pragma unroll
            for (int j = 0; j < 4; j++) {
                sc[f][j][0] = exp2_fast(sc[f][j][0] - mn0);
                sc[f][j][1] = exp2_fast(sc[f][j][1] - mn0);
                sc[f][j][2] = exp2_fast(sc[f][j][2] - mn1);
                sc[f][j][3] = exp2_fast(sc[f][j][3] - mn1);
                rs0 += sc[f][j][0] + sc[f][j][1];
                rs1 += sc[f][j][2] + sc[f][j][3];
            }
            rs0 += __shfl_xor_sync(0xffffffffu, rs0, 1);
            rs0 += __shfl_xor_sync(0xffffffffu, rs0, 2);
            rs1 += __shfl_xor_sync(0xffffffffu, rs1, 1);
            rs1 += __shfl_xor_sync(0xffffffffu, rs1, 2);
            l_[f][0] = l_[f][0] * corr0 + rs0;
            l_[f][1] = l_[f][1] * corr1 + rs1;

#pragma unroll
            for (int nb = 0; nb < 8; nb++) {
                of[f][nb][0] *= corr0; of[f][nb][1] *= corr0;
                of[f][nb][2] *= corr1; of[f][nb][3] *= corr1;
            }
        }

        // PV (shuffle-free): P A-frag = renamed C-frag {c0,c2,c1,c3};
        // V consumed through pi: B-frag rows {s*8+2*t4, s*8+2*t4+1}.
#pragma unroll
        for (int s = 0; s < 4; s++) {
            uint32_t pa[2][4];
#pragma unroll
            for (int f = 0; f < 2; f++) {
                pa[f][0] = f2tf32(sc[f][s][0]);
                pa[f][1] = f2tf32(sc[f][s][2]);
                pa[f][2] = f2tf32(sc[f][s][1]);
                pa[f][3] = f2tf32(sc[f][s][3]);
            }
#pragma unroll
            for (int nb = 0; nb < 8; nb++) {
                uint32_t b0 = __float_as_uint(Vs[s * 8 + 2 * t4][nb * 8 + g]);
                uint32_t b1 = __float_as_uint(Vs[s * 8 + 2 * t4 + 1][nb * 8 + g]);
                mma_tf32(of[0][nb], pa[0], b0, b1);
                mma_tf32(of[1][nb], pa[1], b0, b1);
            }
        }
    }

    // Epilogue: normalize, write g_Xo[b, q, h*64 + d]
#pragma unroll
    for (int f = 0; f < 2; f++) {
        const int rA = rbase + f * 16 + g;
        const int rB = rA + 8;
        const float il0 = 1.0f / l_[f][0];
        const float il1 = 1.0f / l_[f][1];
#pragma unroll
        for (int nb = 0; nb < 8; nb++) {
            float2 o0, o1;
            o0.x = of[f][nb][0] * il0; o0.y = of[f][nb][1] * il0;
            o1.x = of[f][nb][2] * il1; o1.y = of[f][nb][3] * il1;
            const int col = h * DKH + nb * 8 + t4 * 2;
            *(float2*)(g_Xo + (size_t)(b * S_LEN + rA) * DM + col) = o0;
            *(float2*)(g_Xo + (size_t)(b * S_LEN + rB) * DM + col) = o1;
        }
    }
}

// ---------------------------------------------------------------------------
extern "C" void kernel_launch(void* const* d_in, const int* in_sizes, int n_in,
                              void* d_out, int out_size)
{
    const float* query = (const float*)d_in[0];
    const float* key   = (const float*)d_in[1];
    const float* value = (const float*)d_in[2];
    const int*   mask  = (const int*)  d_in[3];
    const float* Wq    = (const float*)d_in[4];
    const float* bq    = (const float*)d_in[5];
    const float* Wk    = (const float*)d_in[6];
    const float* bk    = (const float*)d_in[7];
    const float* Wv    = (const float*)d_in[8];
    const float* bv    = (const float*)d_in[9];
    const float* Wo    = (const float*)d_in[10];
    const float* bo    = (const float*)d_in[11];
    float* out = (float*)d_out;

    float *qp, *xo;
    cudaGetSymbolAddress((void**)&qp, g_Qp);
    cudaGetSymbolAddress((void**)&xo, g_Xo);

    // Q projection: [4096,1024] @ [1024,1024] + bq  (split-tf32, pipelined)
    gemm_mma_bias_kernel<<<dim3(DM / 128, NTOK / 128), 256>>>(query, Wq, bq, qp, NTOK, DM, DM);
    // K and V projections fused into one launch (z=0: K, z=1: V)
    kv_gemm_kernel<<<dim3(1, NTOK / 64, 2), 256>>>(key, Wk, bk, value, Wv, bv);
    // Fused masked MQA attention (tf32 tensor cores, shuffle-free PV)
    attn_mma_kernel<<<dim3(S_LEN / 128, NH, BATCH), 128>>>(mask);
    // Output projection (split-tf32, pipelined)
    gemm_mma_bias_kernel<<<dim3(DM / 128, NTOK / 128), 256>>>(xo, Wo, bo, out, NTOK, DM, DM);
}